// round 3
// baseline (speedup 1.0000x reference)
#include <cuda_runtime.h>
#include <math.h>

#define NNODE 118
#define TT 2048
#define M_ROWS (NNODE*TT)

// ---------------- scratch (device globals; no allocation allowed) ----------
__device__ __align__(256) float g_xpre[(size_t)M_ROWS*512];  // ~495 MB (reused for both layers)
__device__ __align__(256) float g_h1[(size_t)M_ROWS*128];    // ~124 MB
__device__ __align__(256) float g_h2last[NNODE*128];
__device__ __align__(256) float g_vm[2*128];
__device__ __align__(256) float g_flag[1];
__device__ __align__(256) float g_n[NNODE*256];
__device__ __align__(256) float g_Pa[NNODE*192];
__device__ __align__(256) float g_Pb[NNODE*192];
__device__ __align__(256) float g_Qa[NNODE*256];
__device__ __align__(256) float g_Qb[NNODE*256];
__device__ __align__(256) float g_Ra[NNODE*256];
__device__ __align__(256) float g_Rb[NNODE*256];
__device__ __align__(256) float g_alpha[NNODE*NNODE];
__device__ __align__(256) float g_G[4*128*128];

__device__ __forceinline__ float leaky(float z){ return z >= 0.f ? z : 0.01f*z; }

// ---------------- GEMM: C(M,512) = A(M,128) @ W(512,128)^T + b1 + b2 -------
#define GP 68
#define GEMM_SMEM (2*128*GP*4)

__global__ void __launch_bounds__(256) gemm_k(const float* __restrict__ A,
                                              const float* __restrict__ W,
                                              const float* __restrict__ b1,
                                              const float* __restrict__ b2,
                                              float* __restrict__ C)
{
    extern __shared__ float sm[];
    float* As = sm;              // [k][m] padded GP
    float* Ws = sm + 128*GP;     // [k][n] padded GP
    const int tid = threadIdx.x;
    const int mbase = blockIdx.y * 64;
    const int nbase = blockIdx.x * 64;

    const float4* A4 = (const float4*)(A + (size_t)mbase*128);
    const float4* W4 = (const float4*)(W + (size_t)nbase*128);
    #pragma unroll
    for (int r = 0; r < 8; r++) {
        int idx = tid + r*256;          // 0..2047
        int row = idx >> 5;             // 0..63
        int kg  = idx & 31;             // 0..31
        float4 va = A4[row*32 + kg];
        As[(kg*4+0)*GP + row] = va.x;
        As[(kg*4+1)*GP + row] = va.y;
        As[(kg*4+2)*GP + row] = va.z;
        As[(kg*4+3)*GP + row] = va.w;
        float4 vw = W4[row*32 + kg];
        Ws[(kg*4+0)*GP + row] = vw.x;
        Ws[(kg*4+1)*GP + row] = vw.y;
        Ws[(kg*4+2)*GP + row] = vw.z;
        Ws[(kg*4+3)*GP + row] = vw.w;
    }
    __syncthreads();

    const int tx = tid & 15;   // n micro
    const int ty = tid >> 4;   // m micro
    float acc[4][4];
    #pragma unroll
    for (int i = 0; i < 4; i++)
        #pragma unroll
        for (int j = 0; j < 4; j++) acc[i][j] = 0.f;

    const float* Ap = As + ty*4;
    const float* Wp = Ws + tx*4;
    #pragma unroll 8
    for (int k = 0; k < 128; k++) {
        float4 a = *(const float4*)(Ap + k*GP);
        float4 w = *(const float4*)(Wp + k*GP);
        acc[0][0] += a.x*w.x; acc[0][1] += a.x*w.y; acc[0][2] += a.x*w.z; acc[0][3] += a.x*w.w;
        acc[1][0] += a.y*w.x; acc[1][1] += a.y*w.y; acc[1][2] += a.y*w.z; acc[1][3] += a.y*w.w;
        acc[2][0] += a.z*w.x; acc[2][1] += a.z*w.y; acc[2][2] += a.z*w.z; acc[2][3] += a.z*w.w;
        acc[3][0] += a.w*w.x; acc[3][1] += a.w*w.y; acc[3][2] += a.w*w.z; acc[3][3] += a.w*w.w;
    }

    const int col = nbase + tx*4;
    float4 bias;
    bias.x = b1[col+0] + b2[col+0];
    bias.y = b1[col+1] + b2[col+1];
    bias.z = b1[col+2] + b2[col+2];
    bias.w = b1[col+3] + b2[col+3];
    #pragma unroll
    for (int i = 0; i < 4; i++) {
        float4 o;
        o.x = acc[i][0] + bias.x;
        o.y = acc[i][1] + bias.y;
        o.z = acc[i][2] + bias.z;
        o.w = acc[i][3] + bias.w;
        *(float4*)(C + (size_t)(mbase + ty*4 + i)*512 + col) = o;
    }
}

// ---------------- LSTM recurrence: one block per node ----------------------
// thread j owns gate row j of W_hh (512x128). k=0..95 weights in registers,
// k=96..127 in smem (per-thread float4 groups, conflict-free).
#define LSTM_SMEM (8*512*16 + 128*4 + 512*4)

__global__ void __launch_bounds__(512, 1) lstm_rec(const float* __restrict__ xpre,
                                                   const float* __restrict__ Whh,
                                                   float* __restrict__ hout,
                                                   int write_all)
{
    extern __shared__ float sm[];
    float4* ws4 = (float4*)sm;                 // 8 kk-groups * 512 threads
    float*  hs  = sm + 8*512*4;                // h[128]
    float*  gs  = hs + 128;                    // activated gates[512]

    const int j = threadIdx.x;
    const int n = blockIdx.x;

    float wr[96];
    #pragma unroll
    for (int k = 0; k < 96; k++) wr[k] = Whh[j*128 + k];
    #pragma unroll
    for (int kk = 0; kk < 8; kk++)
        ws4[kk*512 + j] = *(const float4*)&Whh[j*128 + 96 + kk*4];

    if (j < 128) hs[j] = 0.f;
    float c = 0.f;
    __syncthreads();

    const float* xp = xpre + (size_t)n*TT*512 + j;
    float xnext = xp[0];

    for (int t = 0; t < TT; t++) {
        float acc = xnext;
        if (t + 1 < TT) xnext = xp[(size_t)(t+1)*512];

        const float4* h4 = (const float4*)hs;
        #pragma unroll
        for (int kk = 0; kk < 24; kk++) {
            float4 h = h4[kk];
            acc += wr[kk*4+0]*h.x + wr[kk*4+1]*h.y + wr[kk*4+2]*h.z + wr[kk*4+3]*h.w;
        }
        #pragma unroll
        for (int kk = 0; kk < 8; kk++) {
            float4 h = h4[24+kk];
            float4 w = ws4[kk*512 + j];
            acc += w.x*h.x + w.y*h.y + w.z*h.z + w.w*h.w;
        }

        float a;
        if (j < 256 || j >= 384) a = 1.f/(1.f + __expf(-acc));  // i, f, o gates
        else                     a = tanhf(acc);                // g gate
        gs[j] = a;
        __syncthreads();

        if (j < 128) {
            float iv = gs[j], fv = gs[j+128], gv = gs[j+256], ov = gs[j+384];
            c = fv*c + iv*gv;
            float hv = ov * tanhf(c);
            hs[j] = hv;
            if (write_all)        hout[((size_t)n*TT + t)*128 + j] = hv;
            else if (t == TT-1)   hout[n*128 + j] = hv;
        }
        __syncthreads();
    }
}

// ---------------- E0: pseudo-message projections + direct outputs ----------
__global__ void prep_kernel(const float* __restrict__ x_tag,
                            const float* __restrict__ pm,
                            const float* __restrict__ Wvm,
                            float* __restrict__ out, int osz)
{
    const int tid = threadIdx.x;  // 128
    __shared__ float pms[768];
    for (int i = tid; i < 768; i += 128) pms[i] = pm[i];
    __syncthreads();

    float base = 0.f;
    for (int k = 0; k < 768; k++) base += pms[k]*Wvm[k*128 + tid];
    g_vm[tid]       = leaky(base);
    g_vm[128 + tid] = leaky(base + Wvm[768*128 + tid]);

    if (tid < NNODE) {
        int o;
        o = 236 + tid*2 + 0; if (o < osz) out[o] = x_tag[tid*3+0];
        o = 236 + tid*2 + 1; if (o < osz) out[o] = x_tag[tid*3+1];
        float a = x_tag[tid*3+2];
        o = 474 + tid; if (o < osz) out[o] = (a == 0.f) ? 1.f : 0.f;
        o = 592 + tid; if (o < osz) out[o] = (a == 1.f) ? 1.f : 0.f;
    }
    if (tid == 0) {
        int cnt = 0;
        for (int i = 0; i < NNODE; i++) if (x_tag[i*3+2] == 0.f) cnt++;
        g_flag[0] = (cnt > 0) ? 1.f : 0.f;
    }
}

// ---------------- Gram matrices for l_ort -----------------------------
__global__ void gram_kernel(const float* __restrict__ Wum, const float* __restrict__ Wvm,
                            const float* __restrict__ Wup, const float* __restrict__ Wvp)
{
    const int bid = blockIdx.x;
    const int mat = bid >> 7;
    const int k   = bid & 127;
    const int l   = threadIdx.x;  // 128
    const float* W; int rows;
    if      (mat == 0) { W = Wum; rows = 769; }
    else if (mat == 1) { W = Wvm; rows = 769; }
    else if (mat == 2) { W = Wup; rows = 128; }
    else               { W = Wvp; rows = 128; }
    float acc = 0.f;
    for (int i = 0; i < rows; i++) acc += W[i*128 + k] * W[i*128 + l];
    g_G[mat*16384 + k*128 + l] = acc;
}

// ---------------- E1: per-node MLP chain -> n -------------------------
__global__ void node_kernel(const float* __restrict__ x_tag,
                            const float* __restrict__ Wup,
                            const float* __restrict__ W_hyb, const float* __restrict__ b_hyb,
                            const float* __restrict__ W_act, const float* __restrict__ b_act,
                            const float* __restrict__ W_inact, const float* __restrict__ b_inact)
{
    const int n = blockIdx.x, tid = threadIdx.x;  // 256
    __shared__ float p[128], up[128], vm_s[128], hh[256];
    const float act = x_tag[n*3+2];
    if (tid < 128) {
        p[tid]    = leaky(g_h2last[n*128 + tid]);
        vm_s[tid] = (act == 1.f) ? g_vm[128 + tid] : g_vm[tid];
    }
    __syncthreads();
    if (tid < 128) {
        float a = 0.f;
        for (int k = 0; k < 128; k++) a += p[k]*Wup[k*128 + tid];
        up[tid] = leaky(a);
    }
    __syncthreads();
    {
        float a = b_hyb[tid];
        for (int k = 0; k < 128; k++) {
            float u_ = up[k], v_ = vm_s[k];
            a += u_*W_hyb[k*256 + tid] + (u_ + v_)*W_hyb[(128+k)*256 + tid] + v_*W_hyb[(256+k)*256 + tid];
        }
        hh[tid] = leaky(a);
    }
    __syncthreads();
    {
        float na = b_act[tid], ni = b_inact[tid];
        for (int k = 0; k < 256; k++) {
            float h_ = hh[k];
            na += h_*W_act[k*256 + tid];
            ni += h_*W_inact[k*256 + tid];
        }
        na += x_tag[n*3+0]*W_act[256*256 + tid] + x_tag[n*3+1]*W_act[257*256 + tid];
        g_n[n*256 + tid] = leaky(na*(1.f - act) + ni*act);
    }
}

// ---------------- E2: per-node pair projections -----------------------
__global__ void proj_kernel(const float* __restrict__ Wphin,
                            const float* __restrict__ Won,
                            const float* __restrict__ Weo)
{
    const int n = blockIdx.x, tid = threadIdx.x;  // 256
    __shared__ float nn_s[256];
    nn_s[tid] = g_n[n*256 + tid];
    __syncthreads();
    if (tid < 192) {
        float pb = 0.f, pa = 0.f;
        for (int k = 0; k < 256; k++) {
            float v = nn_s[k];
            pb += v*Wphin[k*192 + tid];
            pa += v*Wphin[(256+k)*192 + tid];
        }
        g_Pb[n*192 + tid] = pb;
        g_Pa[n*192 + tid] = pa;
    }
    float qb = 0.f, qa = 0.f, rb = 0.f, ra = 0.f;
    for (int k = 0; k < 256; k++) {
        float v = nn_s[k];
        qb += v*Won[k*256 + tid];
        qa += v*Won[(256+k)*256 + tid];
        rb += v*Weo[(256+k)*256 + tid];
        ra += v*Weo[(512+k)*256 + tid];
    }
    g_Qb[n*256 + tid] = qb;
    g_Qa[n*256 + tid] = qa;
    g_Rb[n*256 + tid] = rb;
    g_Ra[n*256 + tid] = ra;
}

// ---------------- E3: phi column + masked softmaxes -> alpha ----------
__device__ __forceinline__ float blockmax128(float v, float* red){
    int tid = threadIdx.x; red[tid] = v; __syncthreads();
    #pragma unroll
    for (int s = 64; s > 0; s >>= 1) { if (tid < s) red[tid] = fmaxf(red[tid], red[tid+s]); __syncthreads(); }
    float r = red[0]; __syncthreads(); return r;
}
__device__ __forceinline__ float blocksum128(float v, float* red){
    int tid = threadIdx.x; red[tid] = v; __syncthreads();
    #pragma unroll
    for (int s = 64; s > 0; s >>= 1) { if (tid < s) red[tid] += red[tid+s]; __syncthreads(); }
    float r = red[0]; __syncthreads(); return r;
}

__global__ void phi_alpha_kernel(const float* __restrict__ x_tag,
                                 const float* __restrict__ aphi)
{
    const int b = blockIdx.x;
    const int tid = threadIdx.x;  // 128
    __shared__ float pb_s[192], ap_s[192], red[128];
    for (int i = tid; i < 192; i += 128) { pb_s[i] = g_Pb[b*192 + i]; ap_s[i] = aphi[i]; }
    __syncthreads();

    float ph = 0.f, v1 = 0.f;
    if (tid < NNODE) {
        const float* pa = g_Pa + tid*192;
        #pragma unroll 8
        for (int d = 0; d < 192; d++) ph += leaky(pb_s[d] + pa[d]) * ap_s[d];
        v1 = (x_tag[tid*3+2] == 0.f) ? 1.f : 0.f;
    }

    const float NEG = -1000000000.f;
    float m1 = (tid < NNODE) ? (v1 > 0.f ? ph : NEG) : -INFINITY;
    float m0 = (tid < NNODE) ? (v1 > 0.f ? NEG : ph) : -INFINITY;
    float ma = (tid < NNODE) ? ph : -INFINITY;

    float mx = blockmax128(m1, red);
    float e  = (tid < NNODE) ? __expf(m1 - mx) : 0.f;
    float s  = blocksum128(e, red);
    float sm1 = e / s;

    mx = blockmax128(m0, red);
    e  = (tid < NNODE) ? __expf(m0 - mx) : 0.f;
    s  = blocksum128(e, red);
    float sm0 = e / s;

    mx = blockmax128(ma, red);
    e  = (tid < NNODE) ? __expf(ma - mx) : 0.f;
    s  = blocksum128(e, red);
    float sma = e / s;

    if (tid < NNODE) {
        float a = (g_flag[0] > 0.f) ? (v1 > 0.f ? sm1 : sm0) : sma;
        g_alpha[tid*NNODE + b] = a;
    }
}

// ---------------- E4: hyper messages + y_hat --------------------------
__global__ void hyper_kernel(const float* __restrict__ x_tag,
                             const float* __restrict__ Weo,
                             const float* __restrict__ Wi,
                             const float* __restrict__ bi,
                             float* __restrict__ out, int osz)
{
    const int n = blockIdx.x, tid = threadIdx.x;  // 256
    __shared__ float qa[256], ra[256], nn_s[256], u[256], al[NNODE], red[256];
    qa[tid]   = g_Qa[n*256 + tid];
    ra[tid]   = g_Ra[n*256 + tid];
    nn_s[tid] = g_n[n*256 + tid];
    if (tid < NNODE) al[tid] = g_alpha[n*NNODE + tid];
    __syncthreads();

    float uacc = 0.f, racc = 0.f, alsum = 0.f;
    const float qad = qa[tid];
    for (int j = 0; j < NNODE; j++) {
        float a_ = al[j];
        uacc  += a_ * leaky(g_Qb[j*256 + tid] + qad);
        racc  += a_ * g_Rb[j*256 + tid];
        alsum += a_;
    }
    u[tid] = uacc;
    __syncthreads();

    float T = racc + alsum*ra[tid];
    for (int k = 0; k < 256; k++) T += u[k]*Weo[k*256 + tid];

    const float act = x_tag[n*3+2];
    float hm0 = leaky(act*T);
    float hm1 = leaky((1.f - act)*T);

    const float* Win = Wi + (size_t)n*768*2;
    float p0 = nn_s[tid]*Win[tid*2+0] + hm0*Win[(256+tid)*2+0] + hm1*Win[(512+tid)*2+0];
    float p1 = nn_s[tid]*Win[tid*2+1] + hm0*Win[(256+tid)*2+1] + hm1*Win[(512+tid)*2+1];

    red[tid] = p0; __syncthreads();
    #pragma unroll
    for (int s = 128; s > 0; s >>= 1) { if (tid < s) red[tid] += red[tid+s]; __syncthreads(); }
    float y0 = red[0] + bi[n*2+0]; __syncthreads();

    red[tid] = p1; __syncthreads();
    #pragma unroll
    for (int s = 128; s > 0; s >>= 1) { if (tid < s) red[tid] += red[tid+s]; __syncthreads(); }
    float y1 = red[0] + bi[n*2+1];

    if (tid == 0) {
        float mx = fmaxf(y0, y1);
        float e0 = __expf(y0 - mx), e1 = __expf(y1 - mx);
        int o;
        o = n*2+0; if (o < osz) out[o] = e0/(e0+e1);
        o = n*2+1; if (o < osz) out[o] = e1/(e0+e1);
    }
}

// ---------------- E5: l_ort + l_pol -----------------------------------
__global__ void finals_kernel(const float* __restrict__ x_tag,
                              float* __restrict__ out, int osz)
{
    const int tid = threadIdx.x;  // 256
    __shared__ float red[256], w[NNODE];

    float s1 = 0.f, s2 = 0.f;
    for (int i = tid; i < 16384; i += 256) {
        s1 += g_G[i]          * g_G[16384 + i];
        s2 += g_G[32768 + i]  * g_G[49152 + i];
    }
    red[tid] = s1; __syncthreads();
    #pragma unroll
    for (int s = 128; s > 0; s >>= 1) { if (tid < s) red[tid] += red[tid+s]; __syncthreads(); }
    float S1 = red[0]; __syncthreads();
    red[tid] = s2; __syncthreads();
    #pragma unroll
    for (int s = 128; s > 0; s >>= 1) { if (tid < s) red[tid] += red[tid+s]; __syncthreads(); }
    float S2 = red[0]; __syncthreads();
    if (tid == 0 && 472 < osz) out[472] = sqrtf(S1) + sqrtf(S2);

    if (tid < NNODE) {
        float nr = 0.f;
        const float* np = g_n + tid*256;
        for (int d = 0; d < 256; d++) nr += np[d]*np[d];
        nr = fmaxf(sqrtf(nr), 1e-8f);
        float diff = x_tag[tid*3+1] - x_tag[tid*3+0];
        float sg = (diff > 0.f ? 1.f : (diff < 0.f ? -1.f : 0.f));
        sg *= (x_tag[tid*3+2] == 0.f) ? 1.f : 0.f;
        w[tid] = sg / nr;
    }
    __syncthreads();
    float v = 0.f;
    for (int i = 0; i < NNODE; i++) v += w[i]*g_n[i*256 + tid];
    red[tid] = v*v; __syncthreads();
    #pragma unroll
    for (int s = 128; s > 0; s >>= 1) { if (tid < s) red[tid] += red[tid+s]; __syncthreads(); }
    if (tid == 0 && 473 < osz) out[473] = red[0];
}

// ---------------- launch ----------------------------------------------
extern "C" void kernel_launch(void* const* d_in, const int* in_sizes, int n_in,
                              void* d_out, int out_size)
{
    const float* x       = (const float*)d_in[0];
    const float* x_tag   = (const float*)d_in[1];
    const float* W_ih0   = (const float*)d_in[2];
    const float* W_hh0   = (const float*)d_in[3];
    const float* b_ih0   = (const float*)d_in[4];
    const float* b_hh0   = (const float*)d_in[5];
    const float* W_ih1   = (const float*)d_in[6];
    const float* W_hh1   = (const float*)d_in[7];
    const float* b_ih1   = (const float*)d_in[8];
    const float* b_hh1   = (const float*)d_in[9];
    const float* pm      = (const float*)d_in[10];
    const float* Wum     = (const float*)d_in[11];
    const float* Wvm     = (const float*)d_in[12];
    const float* Wup     = (const float*)d_in[13];
    const float* Wvp     = (const float*)d_in[14];
    const float* W_hyb   = (const float*)d_in[15];
    const float* b_hyb   = (const float*)d_in[16];
    const float* W_act   = (const float*)d_in[17];
    const float* b_act   = (const float*)d_in[18];
    const float* W_inact = (const float*)d_in[19];
    const float* b_inact = (const float*)d_in[20];
    const float* Wphin   = (const float*)d_in[21];
    const float* aphi    = (const float*)d_in[22];
    const float* Won     = (const float*)d_in[23];
    const float* Weo     = (const float*)d_in[24];
    const float* Wi      = (const float*)d_in[25];
    const float* bi      = (const float*)d_in[26];
    float* out = (float*)d_out;

    float *xpre = nullptr, *h1 = nullptr, *h2last = nullptr;
    cudaGetSymbolAddress((void**)&xpre,   g_xpre);
    cudaGetSymbolAddress((void**)&h1,     g_h1);
    cudaGetSymbolAddress((void**)&h2last, g_h2last);

    cudaFuncSetAttribute(gemm_k,   cudaFuncAttributeMaxDynamicSharedMemorySize, GEMM_SMEM);
    cudaFuncSetAttribute(lstm_rec, cudaFuncAttributeMaxDynamicSharedMemorySize, LSTM_SMEM);

    dim3 gg(8, M_ROWS/64);

    // layer 0
    gemm_k<<<gg, 256, GEMM_SMEM>>>(x, W_ih0, b_ih0, b_hh0, xpre);
    lstm_rec<<<NNODE, 512, LSTM_SMEM>>>(xpre, W_hh0, h1, 1);
    // layer 1
    gemm_k<<<gg, 256, GEMM_SMEM>>>(h1, W_ih1, b_ih1, b_hh1, xpre);
    lstm_rec<<<NNODE, 512, LSTM_SMEM>>>(xpre, W_hh1, h2last, 0);

    // epilogue
    prep_kernel<<<1, 128>>>(x_tag, pm, Wvm, out, out_size);
    gram_kernel<<<512, 128>>>(Wum, Wvm, Wup, Wvp);
    node_kernel<<<NNODE, 256>>>(x_tag, Wup, W_hyb, b_hyb, W_act, b_act, W_inact, b_inact);
    proj_kernel<<<NNODE, 256>>>(Wphin, Won, Weo);
    phi_alpha_kernel<<<NNODE, 128>>>(x_tag, aphi);
    hyper_kernel<<<NNODE, 256>>>(x_tag, Weo, Wi, bi, out, out_size);
    finals_kernel<<<1, 256>>>(x_tag, out, out_size);
}

// round 5
// speedup vs baseline: 1.0940x; 1.0940x over previous
#include <cuda_runtime.h>
#include <math.h>

#define NNODE 118
#define TT 2048
#define M_ROWS (NNODE*TT)

typedef unsigned long long ull;
union F2U { ull u; float2 f; };

__device__ __forceinline__ ull pk2(float x, float y){ ull r; asm("mov.b64 %0, {%1,%2};" : "=l"(r) : "f"(x), "f"(y)); return r; }
__device__ __forceinline__ ull dupf(float x){ ull r; asm("mov.b64 %0, {%1,%1};" : "=l"(r) : "f"(x)); return r; }
__device__ __forceinline__ void fma2(ull& d, ull a, ull b){ asm("fma.rn.f32x2 %0, %1, %2, %0;" : "+l"(d) : "l"(a), "l"(b)); }

// ---------------- scratch (device globals; no allocation allowed) ----------
__device__ __align__(256) float g_xpre[(size_t)M_ROWS*512];
__device__ __align__(256) float g_h1[(size_t)M_ROWS*128];
__device__ __align__(256) float g_h2last[NNODE*128];
__device__ __align__(256) float g_vm[2*128];
__device__ __align__(256) float g_flag[1];
__device__ __align__(256) float g_n[NNODE*256];
__device__ __align__(256) float g_Pa[NNODE*192];
__device__ __align__(256) float g_Pb[NNODE*192];
__device__ __align__(256) float g_Qa[NNODE*256];
__device__ __align__(256) float g_Qb[NNODE*256];
__device__ __align__(256) float g_Ra[NNODE*256];
__device__ __align__(256) float g_Rb[NNODE*256];
__device__ __align__(256) float g_alpha[NNODE*NNODE];
__device__ __align__(256) float g_G[4*128*128];

__device__ __forceinline__ float leaky(float z){ return z >= 0.f ? z : 0.01f*z; }
__device__ __forceinline__ float fast_sig(float x){ return __fdividef(1.f, 1.f + __expf(-x)); }
__device__ __forceinline__ float fast_tanh(float x){
    float t = __expf(-2.f*fabsf(x));
    float r = __fdividef(1.f - t, 1.f + t);
    return copysignf(r, x);
}

// ---------------- GEMM: C(M,512) = A(M,128) @ W(512,128)^T + b1 + b2 -------
// 128x128 block tile, 8x8 micro tile, f32x2 FMA. Pad must be multiple of 4
// so float4 smem loads stay 16B-aligned.
#define GP2 132
#define GEMM_SMEM (2*128*GP2*4)

__global__ void __launch_bounds__(256) gemm_k(const float* __restrict__ A,
                                              const float* __restrict__ W,
                                              const float* __restrict__ b1,
                                              const float* __restrict__ b2,
                                              float* __restrict__ C)
{
    extern __shared__ float sm[];
    float* As = sm;               // [k][m] pad GP2
    float* Ws = sm + 128*GP2;     // [k][n] pad GP2
    const int tid = threadIdx.x;
    const int mbase = blockIdx.y * 128;
    const int nbase = blockIdx.x * 128;

    const float4* A4 = (const float4*)(A + (size_t)mbase*128);
    const float4* W4 = (const float4*)(W + (size_t)nbase*128);
    #pragma unroll
    for (int r = 0; r < 16; r++) {
        int idx = tid + r*256;          // 0..4095
        int row = idx >> 5;             // 0..127
        int kg  = idx & 31;             // 0..31
        float4 va = A4[idx];
        As[(4*kg+0)*GP2 + row] = va.x;
        As[(4*kg+1)*GP2 + row] = va.y;
        As[(4*kg+2)*GP2 + row] = va.z;
        As[(4*kg+3)*GP2 + row] = va.w;
        float4 vw = W4[idx];
        Ws[(4*kg+0)*GP2 + row] = vw.x;
        Ws[(4*kg+1)*GP2 + row] = vw.y;
        Ws[(4*kg+2)*GP2 + row] = vw.z;
        Ws[(4*kg+3)*GP2 + row] = vw.w;
    }
    __syncthreads();

    const int tx = tid & 15;   // n micro
    const int ty = tid >> 4;   // m micro
    const int m0 = ty*8, n0 = tx*8;

    F2U acc[4][8];   // [row-pair][col], .f.x=row 2p, .f.y=row 2p+1
    #pragma unroll
    for (int p = 0; p < 4; p++)
        #pragma unroll
        for (int j = 0; j < 8; j++) acc[p][j].u = 0ull;

    #pragma unroll 8
    for (int k = 0; k < 128; k++) {
        const float4 a0 = *(const float4*)(As + k*GP2 + m0);
        const float4 a1 = *(const float4*)(As + k*GP2 + m0 + 4);
        const float4 w0 = *(const float4*)(Ws + k*GP2 + n0);
        const float4 w1 = *(const float4*)(Ws + k*GP2 + n0 + 4);
        ull ap0 = pk2(a0.x, a0.y), ap1 = pk2(a0.z, a0.w);
        ull ap2 = pk2(a1.x, a1.y), ap3 = pk2(a1.z, a1.w);
        ull wd;
        wd = dupf(w0.x); fma2(acc[0][0].u, ap0, wd); fma2(acc[1][0].u, ap1, wd); fma2(acc[2][0].u, ap2, wd); fma2(acc[3][0].u, ap3, wd);
        wd = dupf(w0.y); fma2(acc[0][1].u, ap0, wd); fma2(acc[1][1].u, ap1, wd); fma2(acc[2][1].u, ap2, wd); fma2(acc[3][1].u, ap3, wd);
        wd = dupf(w0.z); fma2(acc[0][2].u, ap0, wd); fma2(acc[1][2].u, ap1, wd); fma2(acc[2][2].u, ap2, wd); fma2(acc[3][2].u, ap3, wd);
        wd = dupf(w0.w); fma2(acc[0][3].u, ap0, wd); fma2(acc[1][3].u, ap1, wd); fma2(acc[2][3].u, ap2, wd); fma2(acc[3][3].u, ap3, wd);
        wd = dupf(w1.x); fma2(acc[0][4].u, ap0, wd); fma2(acc[1][4].u, ap1, wd); fma2(acc[2][4].u, ap2, wd); fma2(acc[3][4].u, ap3, wd);
        wd = dupf(w1.y); fma2(acc[0][5].u, ap0, wd); fma2(acc[1][5].u, ap1, wd); fma2(acc[2][5].u, ap2, wd); fma2(acc[3][5].u, ap3, wd);
        wd = dupf(w1.z); fma2(acc[0][6].u, ap0, wd); fma2(acc[1][6].u, ap1, wd); fma2(acc[2][6].u, ap2, wd); fma2(acc[3][6].u, ap3, wd);
        wd = dupf(w1.w); fma2(acc[0][7].u, ap0, wd); fma2(acc[1][7].u, ap1, wd); fma2(acc[2][7].u, ap2, wd); fma2(acc[3][7].u, ap3, wd);
    }

    const int col = nbase + n0;
    float bias[8];
    #pragma unroll
    for (int c = 0; c < 8; c++) bias[c] = b1[col+c] + b2[col+c];

    #pragma unroll
    for (int p = 0; p < 4; p++) {
        float4 o;
        float* r0 = C + (size_t)(mbase + m0 + 2*p)*512 + col;
        float* r1 = r0 + 512;
        o.x = acc[p][0].f.x + bias[0]; o.y = acc[p][1].f.x + bias[1];
        o.z = acc[p][2].f.x + bias[2]; o.w = acc[p][3].f.x + bias[3];
        *(float4*)(r0) = o;
        o.x = acc[p][4].f.x + bias[4]; o.y = acc[p][5].f.x + bias[5];
        o.z = acc[p][6].f.x + bias[6]; o.w = acc[p][7].f.x + bias[7];
        *(float4*)(r0 + 4) = o;
        o.x = acc[p][0].f.y + bias[0]; o.y = acc[p][1].f.y + bias[1];
        o.z = acc[p][2].f.y + bias[2]; o.w = acc[p][3].f.y + bias[3];
        *(float4*)(r1) = o;
        o.x = acc[p][4].f.y + bias[4]; o.y = acc[p][5].f.y + bias[5];
        o.z = acc[p][6].f.y + bias[6]; o.w = acc[p][7].f.y + bias[7];
        *(float4*)(r1 + 4) = o;
    }
}

// ---------------- LSTM recurrence: one block per node ----------------------
// thread j owns gate row j (512 rows). k=0..95 weights in regs (48 ull),
// k=96..127 in smem. All dots via f32x2. Redundant c per thread (4 replicas).
#define LSTM_SMEM (8*512*16 + 128*4 + 512*4 + 64)

__global__ void __launch_bounds__(512, 1) lstm_rec(const float* __restrict__ xpre,
                                                   const float* __restrict__ Whh,
                                                   float* __restrict__ hout,
                                                   int write_all)
{
    extern __shared__ float sm[];
    ulonglong2* ws2 = (ulonglong2*)sm;           // [8][512] (k=96..127)
    float* hs = sm + 8*512*4;                    // h[128]
    float* gs = hs + 128;                        // activated gates[512]

    const int j = threadIdx.x;
    const int n = blockIdx.x;
    const int cell = j & 127;
    const int gate = j >> 7;                     // warp-uniform

    // load weights: row j of Whh (128 floats = 32 ulonglong2)
    const ulonglong2* wg = (const ulonglong2*)(Whh + j*128);
    ull wr[48];
    #pragma unroll
    for (int g = 0; g < 24; g++) { ulonglong2 v = wg[g]; wr[2*g] = v.x; wr[2*g+1] = v.y; }
    #pragma unroll
    for (int g = 0; g < 8; g++) ws2[g*512 + j] = wg[24+g];

    if (j < 128) hs[j] = 0.f;
    float c = 0.f;
    __syncthreads();

    const float* xp = xpre + (size_t)n*TT*512 + j;
    float xnext = xp[0];
    float* hw = hout + (size_t)n*(write_all ? TT : 1)*128 + cell;

    for (int t = 0; t < TT; t++) {
        F2U A0, A1, A2, A3;
        A0.u = pk2(xnext, 0.f); A1.u = 0ull; A2.u = 0ull; A3.u = 0ull;
        if (t + 1 < TT) xnext = xp[(size_t)(t+1)*512];

        const ulonglong2* h2 = (const ulonglong2*)hs;
        #pragma unroll
        for (int g = 0; g < 24; g += 2) {
            ulonglong2 hv0 = h2[g];
            ulonglong2 hv1 = h2[g+1];
            fma2(A0.u, wr[2*g],   hv0.x);
            fma2(A1.u, wr[2*g+1], hv0.y);
            fma2(A2.u, wr[2*g+2], hv1.x);
            fma2(A3.u, wr[2*g+3], hv1.y);
        }
        #pragma unroll
        for (int g = 0; g < 8; g += 2) {
            ulonglong2 wv0 = ws2[g*512 + j];
            ulonglong2 wv1 = ws2[(g+1)*512 + j];
            ulonglong2 hv0 = h2[24+g];
            ulonglong2 hv1 = h2[25+g];
            fma2(A0.u, wv0.x, hv0.x);
            fma2(A1.u, wv0.y, hv0.y);
            fma2(A2.u, wv1.x, hv1.x);
            fma2(A3.u, wv1.y, hv1.y);
        }
        float acc = (A0.f.x + A0.f.y) + (A1.f.x + A1.f.y)
                  + (A2.f.x + A2.f.y) + (A3.f.x + A3.f.y);

        gs[j] = (gate == 2) ? fast_tanh(acc) : fast_sig(acc);
        __syncthreads();

        // every thread updates its replica of c for cell = j&127
        float iv = gs[cell], fv = gs[cell+128], gv = gs[cell+256], ov = gs[cell+384];
        c = fv*c + iv*gv;
        float hv = ov * fast_tanh(c);
        if (j < 128) {
            hs[j] = hv;
            if (write_all)      hw[(size_t)t*128] = hv;
            else if (t == TT-1) hw[0] = hv;
        }
        __syncthreads();
    }
}

// ---------------- E0: pseudo-message projections + direct outputs ----------
__global__ void prep_kernel(const float* __restrict__ x_tag,
                            const float* __restrict__ pm,
                            const float* __restrict__ Wvm,
                            float* __restrict__ out, int osz)
{
    const int tid = threadIdx.x;  // 128
    __shared__ float pms[768];
    for (int i = tid; i < 768; i += 128) pms[i] = pm[i];
    __syncthreads();

    float base = 0.f;
    for (int k = 0; k < 768; k++) base += pms[k]*Wvm[k*128 + tid];
    g_vm[tid]       = leaky(base);
    g_vm[128 + tid] = leaky(base + Wvm[768*128 + tid]);

    if (tid < NNODE) {
        int o;
        o = 236 + tid*2 + 0; if (o < osz) out[o] = x_tag[tid*3+0];
        o = 236 + tid*2 + 1; if (o < osz) out[o] = x_tag[tid*3+1];
        float a = x_tag[tid*3+2];
        o = 474 + tid; if (o < osz) out[o] = (a == 0.f) ? 1.f : 0.f;
        o = 592 + tid; if (o < osz) out[o] = (a == 1.f) ? 1.f : 0.f;
    }
    if (tid == 0) {
        int cnt = 0;
        for (int i = 0; i < NNODE; i++) if (x_tag[i*3+2] == 0.f) cnt++;
        g_flag[0] = (cnt > 0) ? 1.f : 0.f;
    }
}

// ---------------- Gram matrices for l_ort -----------------------------
__global__ void gram_kernel(const float* __restrict__ Wum, const float* __restrict__ Wvm,
                            const float* __restrict__ Wup, const float* __restrict__ Wvp)
{
    const int bid = blockIdx.x;
    const int mat = bid >> 7;
    const int k   = bid & 127;
    const int l   = threadIdx.x;  // 128
    const float* W; int rows;
    if      (mat == 0) { W = Wum; rows = 769; }
    else if (mat == 1) { W = Wvm; rows = 769; }
    else if (mat == 2) { W = Wup; rows = 128; }
    else               { W = Wvp; rows = 128; }
    float acc = 0.f;
    for (int i = 0; i < rows; i++) acc += W[i*128 + k] * W[i*128 + l];
    g_G[mat*16384 + k*128 + l] = acc;
}

// ---------------- E1: per-node MLP chain -> n -------------------------
__global__ void node_kernel(const float* __restrict__ x_tag,
                            const float* __restrict__ Wup,
                            const float* __restrict__ W_hyb, const float* __restrict__ b_hyb,
                            const float* __restrict__ W_act, const float* __restrict__ b_act,
                            const float* __restrict__ W_inact, const float* __restrict__ b_inact)
{
    const int n = blockIdx.x, tid = threadIdx.x;  // 256
    __shared__ float p[128], up[128], vm_s[128], hh[256];
    const float act = x_tag[n*3+2];
    if (tid < 128) {
        p[tid]    = leaky(g_h2last[n*128 + tid]);
        vm_s[tid] = (act == 1.f) ? g_vm[128 + tid] : g_vm[tid];
    }
    __syncthreads();
    if (tid < 128) {
        float a = 0.f;
        for (int k = 0; k < 128; k++) a += p[k]*Wup[k*128 + tid];
        up[tid] = leaky(a);
    }
    __syncthreads();
    {
        float a = b_hyb[tid];
        for (int k = 0; k < 128; k++) {
            float u_ = up[k], v_ = vm_s[k];
            a += u_*W_hyb[k*256 + tid] + (u_ + v_)*W_hyb[(128+k)*256 + tid] + v_*W_hyb[(256+k)*256 + tid];
        }
        hh[tid] = leaky(a);
    }
    __syncthreads();
    {
        float na = b_act[tid], ni = b_inact[tid];
        for (int k = 0; k < 256; k++) {
            float h_ = hh[k];
            na += h_*W_act[k*256 + tid];
            ni += h_*W_inact[k*256 + tid];
        }
        na += x_tag[n*3+0]*W_act[256*256 + tid] + x_tag[n*3+1]*W_act[257*256 + tid];
        g_n[n*256 + tid] = leaky(na*(1.f - act) + ni*act);
    }
}

// ---------------- E2: per-node pair projections -----------------------
__global__ void proj_kernel(const float* __restrict__ Wphin,
                            const float* __restrict__ Won,
                            const float* __restrict__ Weo)
{
    const int n = blockIdx.x, tid = threadIdx.x;  // 256
    __shared__ float nn_s[256];
    nn_s[tid] = g_n[n*256 + tid];
    __syncthreads();
    if (tid < 192) {
        float pb = 0.f, pa = 0.f;
        for (int k = 0; k < 256; k++) {
            float v = nn_s[k];
            pb += v*Wphin[k*192 + tid];
            pa += v*Wphin[(256+k)*192 + tid];
        }
        g_Pb[n*192 + tid] = pb;
        g_Pa[n*192 + tid] = pa;
    }
    float qb = 0.f, qa = 0.f, rb = 0.f, ra = 0.f;
    for (int k = 0; k < 256; k++) {
        float v = nn_s[k];
        qb += v*Won[k*256 + tid];
        qa += v*Won[(256+k)*256 + tid];
        rb += v*Weo[(256+k)*256 + tid];
        ra += v*Weo[(512+k)*256 + tid];
    }
    g_Qb[n*256 + tid] = qb;
    g_Qa[n*256 + tid] = qa;
    g_Rb[n*256 + tid] = rb;
    g_Ra[n*256 + tid] = ra;
}

// ---------------- E3: phi column + masked softmaxes -> alpha ----------
__device__ __forceinline__ float blockmax128(float v, float* red){
    int tid = threadIdx.x; red[tid] = v; __syncthreads();
    #pragma unroll
    for (int s = 64; s > 0; s >>= 1) { if (tid < s) red[tid] = fmaxf(red[tid], red[tid+s]); __syncthreads(); }
    float r = red[0]; __syncthreads(); return r;
}
__device__ __forceinline__ float blocksum128(float v, float* red){
    int tid = threadIdx.x; red[tid] = v; __syncthreads();
    #pragma unroll
    for (int s = 64; s > 0; s >>= 1) { if (tid < s) red[tid] += red[tid+s]; __syncthreads(); }
    float r = red[0]; __syncthreads(); return r;
}

__global__ void phi_alpha_kernel(const float* __restrict__ x_tag,
                                 const float* __restrict__ aphi)
{
    const int b = blockIdx.x;
    const int tid = threadIdx.x;  // 128
    __shared__ float pb_s[192], ap_s[192], red[128];
    for (int i = tid; i < 192; i += 128) { pb_s[i] = g_Pb[b*192 + i]; ap_s[i] = aphi[i]; }
    __syncthreads();

    float ph = 0.f, v1 = 0.f;
    if (tid < NNODE) {
        const float* pa = g_Pa + tid*192;
        #pragma unroll 8
        for (int d = 0; d < 192; d++) ph += leaky(pb_s[d] + pa[d]) * ap_s[d];
        v1 = (x_tag[tid*3+2] == 0.f) ? 1.f : 0.f;
    }

    const float NEG = -1000000000.f;
    float m1 = (tid < NNODE) ? (v1 > 0.f ? ph : NEG) : -INFINITY;
    float m0 = (tid < NNODE) ? (v1 > 0.f ? NEG : ph) : -INFINITY;
    float ma = (tid < NNODE) ? ph : -INFINITY;

    float mx = blockmax128(m1, red);
    float e  = (tid < NNODE) ? __expf(m1 - mx) : 0.f;
    float s  = blocksum128(e, red);
    float sm1 = e / s;

    mx = blockmax128(m0, red);
    e  = (tid < NNODE) ? __expf(m0 - mx) : 0.f;
    s  = blocksum128(e, red);
    float sm0 = e / s;

    mx = blockmax128(ma, red);
    e  = (tid < NNODE) ? __expf(ma - mx) : 0.f;
    s  = blocksum128(e, red);
    float sma = e / s;

    if (tid < NNODE) {
        float a = (g_flag[0] > 0.f) ? (v1 > 0.f ? sm1 : sm0) : sma;
        g_alpha[tid*NNODE + b] = a;
    }
}

// ---------------- E4: hyper messages + y_hat --------------------------
__global__ void hyper_kernel(const float* __restrict__ x_tag,
                             const float* __restrict__ Weo,
                             const float* __restrict__ Wi,
                             const float* __restrict__ bi,
                             float* __restrict__ out, int osz)
{
    const int n = blockIdx.x, tid = threadIdx.x;  // 256
    __shared__ float qa[256], ra[256], nn_s[256], u[256], al[NNODE], red[256];
    qa[tid]   = g_Qa[n*256 + tid];
    ra[tid]   = g_Ra[n*256 + tid];
    nn_s[tid] = g_n[n*256 + tid];
    if (tid < NNODE) al[tid] = g_alpha[n*NNODE + tid];
    __syncthreads();

    float uacc = 0.f, racc = 0.f, alsum = 0.f;
    const float qad = qa[tid];
    for (int j = 0; j < NNODE; j++) {
        float a_ = al[j];
        uacc  += a_ * leaky(g_Qb[j*256 + tid] + qad);
        racc  += a_ * g_Rb[j*256 + tid];
        alsum += a_;
    }
    u[tid] = uacc;
    __syncthreads();

    float T = racc + alsum*ra[tid];
    for (int k = 0; k < 256; k++) T += u[k]*Weo[k*256 + tid];

    const float act = x_tag[n*3+2];
    float hm0 = leaky(act*T);
    float hm1 = leaky((1.f - act)*T);

    const float* Win = Wi + (size_t)n*768*2;
    float p0 = nn_s[tid]*Win[tid*2+0] + hm0*Win[(256+tid)*2+0] + hm1*Win[(512+tid)*2+0];
    float p1 = nn_s[tid]*Win[tid*2+1] + hm0*Win[(256+tid)*2+1] + hm1*Win[(512+tid)*2+1];

    red[tid] = p0; __syncthreads();
    #pragma unroll
    for (int s = 128; s > 0; s >>= 1) { if (tid < s) red[tid] += red[tid+s]; __syncthreads(); }
    float y0 = red[0] + bi[n*2+0]; __syncthreads();

    red[tid] = p1; __syncthreads();
    #pragma unroll
    for (int s = 128; s > 0; s >>= 1) { if (tid < s) red[tid] += red[tid+s]; __syncthreads(); }
    float y1 = red[0] + bi[n*2+1];

    if (tid == 0) {
        float mx = fmaxf(y0, y1);
        float e0 = __expf(y0 - mx), e1 = __expf(y1 - mx);
        int o;
        o = n*2+0; if (o < osz) out[o] = e0/(e0+e1);
        o = n*2+1; if (o < osz) out[o] = e1/(e0+e1);
    }
}

// ---------------- E5: l_ort + l_pol -----------------------------------
__global__ void finals_kernel(const float* __restrict__ x_tag,
                              float* __restrict__ out, int osz)
{
    const int tid = threadIdx.x;  // 256
    __shared__ float red[256], w[NNODE];

    float s1 = 0.f, s2 = 0.f;
    for (int i = tid; i < 16384; i += 256) {
        s1 += g_G[i]          * g_G[16384 + i];
        s2 += g_G[32768 + i]  * g_G[49152 + i];
    }
    red[tid] = s1; __syncthreads();
    #pragma unroll
    for (int s = 128; s > 0; s >>= 1) { if (tid < s) red[tid] += red[tid+s]; __syncthreads(); }
    float S1 = red[0]; __syncthreads();
    red[tid] = s2; __syncthreads();
    #pragma unroll
    for (int s = 128; s > 0; s >>= 1) { if (tid < s) red[tid] += red[tid+s]; __syncthreads(); }
    float S2 = red[0]; __syncthreads();
    if (tid == 0 && 472 < osz) out[472] = sqrtf(S1) + sqrtf(S2);

    if (tid < NNODE) {
        float nr = 0.f;
        const float* np = g_n + tid*256;
        for (int d = 0; d < 256; d++) nr += np[d]*np[d];
        nr = fmaxf(sqrtf(nr), 1e-8f);
        float diff = x_tag[tid*3+1] - x_tag[tid*3+0];
        float sg = (diff > 0.f ? 1.f : (diff < 0.f ? -1.f : 0.f));
        sg *= (x_tag[tid*3+2] == 0.f) ? 1.f : 0.f;
        w[tid] = sg / nr;
    }
    __syncthreads();
    float v = 0.f;
    for (int i = 0; i < NNODE; i++) v += w[i]*g_n[i*256 + tid];
    red[tid] = v*v; __syncthreads();
    #pragma unroll
    for (int s = 128; s > 0; s >>= 1) { if (tid < s) red[tid] += red[tid+s]; __syncthreads(); }
    if (tid == 0 && 473 < osz) out[473] = red[0];
}

// ---------------- launch ----------------------------------------------
extern "C" void kernel_launch(void* const* d_in, const int* in_sizes, int n_in,
                              void* d_out, int out_size)
{
    const float* x       = (const float*)d_in[0];
    const float* x_tag   = (const float*)d_in[1];
    const float* W_ih0   = (const float*)d_in[2];
    const float* W_hh0   = (const float*)d_in[3];
    const float* b_ih0   = (const float*)d_in[4];
    const float* b_hh0   = (const float*)d_in[5];
    const float* W_ih1   = (const float*)d_in[6];
    const float* W_hh1   = (const float*)d_in[7];
    const float* b_ih1   = (const float*)d_in[8];
    const float* b_hh1   = (const float*)d_in[9];
    const float* pm      = (const float*)d_in[10];
    const float* Wum     = (const float*)d_in[11];
    const float* Wvm     = (const float*)d_in[12];
    const float* Wup     = (const float*)d_in[13];
    const float* Wvp     = (const float*)d_in[14];
    const float* W_hyb   = (const float*)d_in[15];
    const float* b_hyb   = (const float*)d_in[16];
    const float* W_act   = (const float*)d_in[17];
    const float* b_act   = (const float*)d_in[18];
    const float* W_inact = (const float*)d_in[19];
    const float* b_inact = (const float*)d_in[20];
    const float* Wphin   = (const float*)d_in[21];
    const float* aphi    = (const float*)d_in[22];
    const float* Won     = (const float*)d_in[23];
    const float* Weo     = (const float*)d_in[24];
    const float* Wi      = (const float*)d_in[25];
    const float* bi      = (const float*)d_in[26];
    float* out = (float*)d_out;

    float *xpre = nullptr, *h1 = nullptr, *h2last = nullptr;
    cudaGetSymbolAddress((void**)&xpre,   g_xpre);
    cudaGetSymbolAddress((void**)&h1,     g_h1);
    cudaGetSymbolAddress((void**)&h2last, g_h2last);

    cudaFuncSetAttribute(gemm_k,   cudaFuncAttributeMaxDynamicSharedMemorySize, GEMM_SMEM);
    cudaFuncSetAttribute(lstm_rec, cudaFuncAttributeMaxDynamicSharedMemorySize, LSTM_SMEM);

    dim3 gg(4, M_ROWS/128);

    // layer 0
    gemm_k<<<gg, 256, GEMM_SMEM>>>(x, W_ih0, b_ih0, b_hh0, xpre);
    lstm_rec<<<NNODE, 512, LSTM_SMEM>>>(xpre, W_hh0, h1, 1);
    // layer 1
    gemm_k<<<gg, 256, GEMM_SMEM>>>(h1, W_ih1, b_ih1, b_hh1, xpre);
    lstm_rec<<<NNODE, 512, LSTM_SMEM>>>(xpre, W_hh1, h2last, 0);

    // epilogue
    prep_kernel<<<1, 128>>>(x_tag, pm, Wvm, out, out_size);
    gram_kernel<<<512, 128>>>(Wum, Wvm, Wup, Wvp);
    node_kernel<<<NNODE, 256>>>(x_tag, Wup, W_hyb, b_hyb, W_act, b_act, W_inact, b_inact);
    proj_kernel<<<NNODE, 256>>>(Wphin, Won, Weo);
    phi_alpha_kernel<<<NNODE, 128>>>(x_tag, aphi);
    hyper_kernel<<<NNODE, 256>>>(x_tag, Weo, Wi, bi, out, out_size);
    finals_kernel<<<1, 256>>>(x_tag, out, out_size);
}

// round 6
// speedup vs baseline: 1.1282x; 1.0313x over previous
#include <cuda_runtime.h>
#include <math.h>

#define NNODE 118
#define TT 2048
#define M_ROWS (NNODE*TT)

typedef unsigned long long ull;
union F2U { ull u; float2 f; };

__device__ __forceinline__ ull pk2(float x, float y){ ull r; asm("mov.b64 %0, {%1,%2};" : "=l"(r) : "f"(x), "f"(y)); return r; }
__device__ __forceinline__ ull dupf(float x){ ull r; asm("mov.b64 %0, {%1,%1};" : "=l"(r) : "f"(x)); return r; }
__device__ __forceinline__ void fma2(ull& d, ull a, ull b){ asm("fma.rn.f32x2 %0, %1, %2, %0;" : "+l"(d) : "l"(a), "l"(b)); }

// unpack bf16x2 word -> f32x2 (bf16 low half = first/even element)
__device__ __forceinline__ ull unpk(unsigned w){
    unsigned lo = w << 16;
    unsigned hi = w & 0xFFFF0000u;
    ull r; asm("mov.b64 %0, {%1,%2};" : "=l"(r) : "r"(lo), "r"(hi));
    return r;
}
__device__ __forceinline__ unsigned bf1(float f){
    unsigned b = __float_as_uint(f);
    return (b + 0x7FFFu + ((b >> 16) & 1u)) >> 16;   // RNE
}
__device__ __forceinline__ unsigned bfpair(float e, float o){ return bf1(e) | (bf1(o) << 16); }

// ---------------- scratch (device globals; no allocation allowed) ----------
__device__ __align__(256) float g_xpre[(size_t)M_ROWS*512];
__device__ __align__(256) float g_h1[(size_t)M_ROWS*128];
__device__ __align__(256) float g_h2last[NNODE*128];
__device__ __align__(256) float g_vm[2*128];
__device__ __align__(256) float g_flag[1];
__device__ __align__(256) float g_n[NNODE*256];
__device__ __align__(256) float g_Pa[NNODE*192];
__device__ __align__(256) float g_Pb[NNODE*192];
__device__ __align__(256) float g_Qa[NNODE*256];
__device__ __align__(256) float g_Qb[NNODE*256];
__device__ __align__(256) float g_Ra[NNODE*256];
__device__ __align__(256) float g_Rb[NNODE*256];
__device__ __align__(256) float g_alpha[NNODE*NNODE];
__device__ __align__(256) float g_G[4*128*128];

__device__ __forceinline__ float leaky(float z){ return z >= 0.f ? z : 0.01f*z; }

// ---------------- GEMM: C(M,512) = A(M,128) @ W(512,128)^T + b1 + b2 -------
#define GP2 132
#define GEMM_SMEM (2*128*GP2*4)

__global__ void __launch_bounds__(256) gemm_k(const float* __restrict__ A,
                                              const float* __restrict__ W,
                                              const float* __restrict__ b1,
                                              const float* __restrict__ b2,
                                              float* __restrict__ C)
{
    extern __shared__ float sm[];
    float* As = sm;               // [k][m] pad GP2
    float* Ws = sm + 128*GP2;     // [k][n] pad GP2
    const int tid = threadIdx.x;
    const int mbase = blockIdx.y * 128;
    const int nbase = blockIdx.x * 128;

    const float4* A4 = (const float4*)(A + (size_t)mbase*128);
    const float4* W4 = (const float4*)(W + (size_t)nbase*128);
    #pragma unroll
    for (int r = 0; r < 16; r++) {
        int idx = tid + r*256;          // 0..4095
        int row = idx >> 5;             // 0..127
        int kg  = idx & 31;             // 0..31
        float4 va = A4[idx];
        As[(4*kg+0)*GP2 + row] = va.x;
        As[(4*kg+1)*GP2 + row] = va.y;
        As[(4*kg+2)*GP2 + row] = va.z;
        As[(4*kg+3)*GP2 + row] = va.w;
        float4 vw = W4[idx];
        Ws[(4*kg+0)*GP2 + row] = vw.x;
        Ws[(4*kg+1)*GP2 + row] = vw.y;
        Ws[(4*kg+2)*GP2 + row] = vw.z;
        Ws[(4*kg+3)*GP2 + row] = vw.w;
    }
    __syncthreads();

    const int tx = tid & 15;   // n micro
    const int ty = tid >> 4;   // m micro
    const int m0 = ty*8, n0 = tx*8;

    F2U acc[4][8];
    #pragma unroll
    for (int p = 0; p < 4; p++)
        #pragma unroll
        for (int j = 0; j < 8; j++) acc[p][j].u = 0ull;

    #pragma unroll 8
    for (int k = 0; k < 128; k++) {
        const float4 a0 = *(const float4*)(As + k*GP2 + m0);
        const float4 a1 = *(const float4*)(As + k*GP2 + m0 + 4);
        const float4 w0 = *(const float4*)(Ws + k*GP2 + n0);
        const float4 w1 = *(const float4*)(Ws + k*GP2 + n0 + 4);
        ull ap0 = pk2(a0.x, a0.y), ap1 = pk2(a0.z, a0.w);
        ull ap2 = pk2(a1.x, a1.y), ap3 = pk2(a1.z, a1.w);
        ull wd;
        wd = dupf(w0.x); fma2(acc[0][0].u, ap0, wd); fma2(acc[1][0].u, ap1, wd); fma2(acc[2][0].u, ap2, wd); fma2(acc[3][0].u, ap3, wd);
        wd = dupf(w0.y); fma2(acc[0][1].u, ap0, wd); fma2(acc[1][1].u, ap1, wd); fma2(acc[2][1].u, ap2, wd); fma2(acc[3][1].u, ap3, wd);
        wd = dupf(w0.z); fma2(acc[0][2].u, ap0, wd); fma2(acc[1][2].u, ap1, wd); fma2(acc[2][2].u, ap2, wd); fma2(acc[3][2].u, ap3, wd);
        wd = dupf(w0.w); fma2(acc[0][3].u, ap0, wd); fma2(acc[1][3].u, ap1, wd); fma2(acc[2][3].u, ap2, wd); fma2(acc[3][3].u, ap3, wd);
        wd = dupf(w1.x); fma2(acc[0][4].u, ap0, wd); fma2(acc[1][4].u, ap1, wd); fma2(acc[2][4].u, ap2, wd); fma2(acc[3][4].u, ap3, wd);
        wd = dupf(w1.y); fma2(acc[0][5].u, ap0, wd); fma2(acc[1][5].u, ap1, wd); fma2(acc[2][5].u, ap2, wd); fma2(acc[3][5].u, ap3, wd);
        wd = dupf(w1.z); fma2(acc[0][6].u, ap0, wd); fma2(acc[1][6].u, ap1, wd); fma2(acc[2][6].u, ap2, wd); fma2(acc[3][6].u, ap3, wd);
        wd = dupf(w1.w); fma2(acc[0][7].u, ap0, wd); fma2(acc[1][7].u, ap1, wd); fma2(acc[2][7].u, ap2, wd); fma2(acc[3][7].u, ap3, wd);
    }

    const int col = nbase + n0;
    float bias[8];
    #pragma unroll
    for (int c = 0; c < 8; c++) bias[c] = b1[col+c] + b2[col+c];

    #pragma unroll
    for (int p = 0; p < 4; p++) {
        float4 o;
        float* r0 = C + (size_t)(mbase + m0 + 2*p)*512 + col;
        float* r1 = r0 + 512;
        o.x = acc[p][0].f.x + bias[0]; o.y = acc[p][1].f.x + bias[1];
        o.z = acc[p][2].f.x + bias[2]; o.w = acc[p][3].f.x + bias[3];
        *(float4*)(r0) = o;
        o.x = acc[p][4].f.x + bias[4]; o.y = acc[p][5].f.x + bias[5];
        o.z = acc[p][6].f.x + bias[6]; o.w = acc[p][7].f.x + bias[7];
        *(float4*)(r0 + 4) = o;
        o.x = acc[p][0].f.y + bias[0]; o.y = acc[p][1].f.y + bias[1];
        o.z = acc[p][2].f.y + bias[2]; o.w = acc[p][3].f.y + bias[3];
        *(float4*)(r1) = o;
        o.x = acc[p][4].f.y + bias[4]; o.y = acc[p][5].f.y + bias[5];
        o.z = acc[p][6].f.y + bias[6]; o.w = acc[p][7].f.y + bias[7];
        *(float4*)(r1 + 4) = o;
    }
}

// ---------------- LSTM recurrence: one block per node ----------------------
// lane l of warp w owns (gate = l&3, cell = 8w + l>>4...): all 4 gates of a
// cell live in one warp -> cell update via SHFL, ONE barrier per step,
// h double-buffered. k=0..95 weights fp32 in regs, k=96..127 bf16 in smem.
template<int WRITE_ALL>
__global__ void __launch_bounds__(512, 1) lstm_rec(const float* __restrict__ xpre,
                                                   const float* __restrict__ Whh,
                                                   float* __restrict__ hout)
{
    __shared__ __align__(16) float hs[2][128];
    __shared__ __align__(16) uint4 wsb[4*512];   // 32 KB bf16 weight slice

    const int j = threadIdx.x;
    const int n = blockIdx.x;
    const int l = j & 31;
    const int w = j >> 5;
    const int gate = l & 3;
    const int cell = w*8 + (l >> 2);
    const int row  = gate*128 + cell;

    // load weights: row `row` of Whh (128 floats)
    const float* wg = Whh + row*128;
    ull wr[48];
    #pragma unroll
    for (int g = 0; g < 24; g++) {
        float4 v = *(const float4*)(wg + 4*g);
        wr[2*g]   = pk2(v.x, v.y);
        wr[2*g+1] = pk2(v.z, v.w);
    }
    #pragma unroll
    for (int g = 0; g < 4; g++) {
        const float* base = wg + 96 + g*8;
        uint4 pk;
        pk.x = bfpair(base[0], base[1]);
        pk.y = bfpair(base[2], base[3]);
        pk.z = bfpair(base[4], base[5]);
        pk.w = bfpair(base[6], base[7]);
        wsb[g*512 + j] = pk;
    }

    if (j < 128) hs[0][j] = 0.f;
    float c = 0.f;
    __syncthreads();

    const float* xp = xpre + (size_t)n*TT*512 + row;
    float xnext = xp[0];
    float* hw = hout + (WRITE_ALL ? ((size_t)n*TT*128 + cell) : ((size_t)n*128 + cell));

    int p = 0;
    for (int t = 0; t < TT; t++) {
        F2U A0, A1, A2, A3;
        A0.u = pk2(xnext, 0.f); A1.u = 0ull; A2.u = 0ull; A3.u = 0ull;
        if (t + 1 < TT) xnext = xp[(size_t)(t+1)*512];

        const ulonglong2* h2 = (const ulonglong2*)hs[p];
        #pragma unroll
        for (int g = 0; g < 24; g += 2) {
            ulonglong2 hv0 = h2[g];
            ulonglong2 hv1 = h2[g+1];
            fma2(A0.u, wr[2*g],   hv0.x);
            fma2(A1.u, wr[2*g+1], hv0.y);
            fma2(A2.u, wr[2*g+2], hv1.x);
            fma2(A3.u, wr[2*g+3], hv1.y);
        }
        #pragma unroll
        for (int g = 0; g < 4; g++) {
            uint4 wv = wsb[g*512 + j];
            ulonglong2 hv0 = h2[24 + 2*g];
            ulonglong2 hv1 = h2[25 + 2*g];
            fma2(A0.u, unpk(wv.x), hv0.x);
            fma2(A1.u, unpk(wv.y), hv0.y);
            fma2(A2.u, unpk(wv.z), hv1.x);
            fma2(A3.u, unpk(wv.w), hv1.y);
        }
        float acc = (A0.f.x + A0.f.y) + (A1.f.x + A1.f.y)
                  + (A2.f.x + A2.f.y) + (A3.f.x + A3.f.y);

        // branch-free activation: sigmoid for i,f,o; tanh = 2*sig(2x)-1 for g
        const bool isg = (gate == 2);
        float u  = isg ? 2.f*acc : acc;
        float e  = __expf(-u);
        float s  = __fdividef(1.f, 1.f + e);
        float a  = isg ? (2.f*s - 1.f) : s;

        const int base = l & ~3;
        float iv = __shfl_sync(0xFFFFFFFFu, a, base);
        float fv = __shfl_sync(0xFFFFFFFFu, a, base + 1);
        float gv = __shfl_sync(0xFFFFFFFFu, a, base + 2);
        float ov = __shfl_sync(0xFFFFFFFFu, a, base + 3);
        c = fv*c + iv*gv;
        float e2 = __expf(-2.f*c);
        float th = __fdividef(2.f, 1.f + e2) - 1.f;
        float hv = ov * th;
        p ^= 1;
        if (gate == 0) {
            hs[p][cell] = hv;
            if (WRITE_ALL)      hw[(size_t)t*128] = hv;
            else if (t == TT-1) hw[0] = hv;
        }
        __syncthreads();
    }
}

// ---------------- E0: pseudo-message projections + direct outputs ----------
__global__ void prep_kernel(const float* __restrict__ x_tag,
                            const float* __restrict__ pm,
                            const float* __restrict__ Wvm,
                            float* __restrict__ out, int osz)
{
    const int tid = threadIdx.x;  // 128
    __shared__ float pms[768];
    for (int i = tid; i < 768; i += 128) pms[i] = pm[i];
    __syncthreads();

    float base = 0.f;
    for (int k = 0; k < 768; k++) base += pms[k]*Wvm[k*128 + tid];
    g_vm[tid]       = leaky(base);
    g_vm[128 + tid] = leaky(base + Wvm[768*128 + tid]);

    if (tid < NNODE) {
        int o;
        o = 236 + tid*2 + 0; if (o < osz) out[o] = x_tag[tid*3+0];
        o = 236 + tid*2 + 1; if (o < osz) out[o] = x_tag[tid*3+1];
        float a = x_tag[tid*3+2];
        o = 474 + tid; if (o < osz) out[o] = (a == 0.f) ? 1.f : 0.f;
        o = 592 + tid; if (o < osz) out[o] = (a == 1.f) ? 1.f : 0.f;
    }
    if (tid == 0) {
        int cnt = 0;
        for (int i = 0; i < NNODE; i++) if (x_tag[i*3+2] == 0.f) cnt++;
        g_flag[0] = (cnt > 0) ? 1.f : 0.f;
    }
}

// ---------------- Gram matrices for l_ort -----------------------------
__global__ void gram_kernel(const float* __restrict__ Wum, const float* __restrict__ Wvm,
                            const float* __restrict__ Wup, const float* __restrict__ Wvp)
{
    const int bid = blockIdx.x;
    const int mat = bid >> 7;
    const int k   = bid & 127;
    const int l   = threadIdx.x;  // 128
    const float* W; int rows;
    if      (mat == 0) { W = Wum; rows = 769; }
    else if (mat == 1) { W = Wvm; rows = 769; }
    else if (mat == 2) { W = Wup; rows = 128; }
    else               { W = Wvp; rows = 128; }
    float acc = 0.f;
    for (int i = 0; i < rows; i++) acc += W[i*128 + k] * W[i*128 + l];
    g_G[mat*16384 + k*128 + l] = acc;
}

// ---------------- E1: per-node MLP chain -> n -------------------------
__global__ void node_kernel(const float* __restrict__ x_tag,
                            const float* __restrict__ Wup,
                            const float* __restrict__ W_hyb, const float* __restrict__ b_hyb,
                            const float* __restrict__ W_act, const float* __restrict__ b_act,
                            const float* __restrict__ W_inact, const float* __restrict__ b_inact)
{
    const int n = blockIdx.x, tid = threadIdx.x;  // 256
    __shared__ float p[128], up[128], vm_s[128], hh[256];
    const float act = x_tag[n*3+2];
    if (tid < 128) {
        p[tid]    = leaky(g_h2last[n*128 + tid]);
        vm_s[tid] = (act == 1.f) ? g_vm[128 + tid] : g_vm[tid];
    }
    __syncthreads();
    if (tid < 128) {
        float a = 0.f;
        for (int k = 0; k < 128; k++) a += p[k]*Wup[k*128 + tid];
        up[tid] = leaky(a);
    }
    __syncthreads();
    {
        float a = b_hyb[tid];
        for (int k = 0; k < 128; k++) {
            float u_ = up[k], v_ = vm_s[k];
            a += u_*W_hyb[k*256 + tid] + (u_ + v_)*W_hyb[(128+k)*256 + tid] + v_*W_hyb[(256+k)*256 + tid];
        }
        hh[tid] = leaky(a);
    }
    __syncthreads();
    {
        float na = b_act[tid], ni = b_inact[tid];
        for (int k = 0; k < 256; k++) {
            float h_ = hh[k];
            na += h_*W_act[k*256 + tid];
            ni += h_*W_inact[k*256 + tid];
        }
        na += x_tag[n*3+0]*W_act[256*256 + tid] + x_tag[n*3+1]*W_act[257*256 + tid];
        g_n[n*256 + tid] = leaky(na*(1.f - act) + ni*act);
    }
}

// ---------------- E2: per-node pair projections -----------------------
__global__ void proj_kernel(const float* __restrict__ Wphin,
                            const float* __restrict__ Won,
                            const float* __restrict__ Weo)
{
    const int n = blockIdx.x, tid = threadIdx.x;  // 256
    __shared__ float nn_s[256];
    nn_s[tid] = g_n[n*256 + tid];
    __syncthreads();
    if (tid < 192) {
        float pb = 0.f, pa = 0.f;
        for (int k = 0; k < 256; k++) {
            float v = nn_s[k];
            pb += v*Wphin[k*192 + tid];
            pa += v*Wphin[(256+k)*192 + tid];
        }
        g_Pb[n*192 + tid] = pb;
        g_Pa[n*192 + tid] = pa;
    }
    float qb = 0.f, qa = 0.f, rb = 0.f, ra = 0.f;
    for (int k = 0; k < 256; k++) {
        float v = nn_s[k];
        qb += v*Won[k*256 + tid];
        qa += v*Won[(256+k)*256 + tid];
        rb += v*Weo[(256+k)*256 + tid];
        ra += v*Weo[(512+k)*256 + tid];
    }
    g_Qb[n*256 + tid] = qb;
    g_Qa[n*256 + tid] = qa;
    g_Rb[n*256 + tid] = rb;
    g_Ra[n*256 + tid] = ra;
}

// ---------------- E3: phi column + masked softmaxes -> alpha ----------
__device__ __forceinline__ float blockmax128(float v, float* red){
    int tid = threadIdx.x; red[tid] = v; __syncthreads();
    #pragma unroll
    for (int s = 64; s > 0; s >>= 1) { if (tid < s) red[tid] = fmaxf(red[tid], red[tid+s]); __syncthreads(); }
    float r = red[0]; __syncthreads(); return r;
}
__device__ __forceinline__ float blocksum128(float v, float* red){
    int tid = threadIdx.x; red[tid] = v; __syncthreads();
    #pragma unroll
    for (int s = 64; s > 0; s >>= 1) { if (tid < s) red[tid] += red[tid+s]; __syncthreads(); }
    float r = red[0]; __syncthreads(); return r;
}

__global__ void phi_alpha_kernel(const float* __restrict__ x_tag,
                                 const float* __restrict__ aphi)
{
    const int b = blockIdx.x;
    const int tid = threadIdx.x;  // 128
    __shared__ float pb_s[192], ap_s[192], red[128];
    for (int i = tid; i < 192; i += 128) { pb_s[i] = g_Pb[b*192 + i]; ap_s[i] = aphi[i]; }
    __syncthreads();

    float ph = 0.f, v1 = 0.f;
    if (tid < NNODE) {
        const float* pa = g_Pa + tid*192;
        #pragma unroll 8
        for (int d = 0; d < 192; d++) ph += leaky(pb_s[d] + pa[d]) * ap_s[d];
        v1 = (x_tag[tid*3+2] == 0.f) ? 1.f : 0.f;
    }

    const float NEG = -1000000000.f;
    float m1 = (tid < NNODE) ? (v1 > 0.f ? ph : NEG) : -INFINITY;
    float m0 = (tid < NNODE) ? (v1 > 0.f ? NEG : ph) : -INFINITY;
    float ma = (tid < NNODE) ? ph : -INFINITY;

    float mx = blockmax128(m1, red);
    float e  = (tid < NNODE) ? __expf(m1 - mx) : 0.f;
    float s  = blocksum128(e, red);
    float sm1 = e / s;

    mx = blockmax128(m0, red);
    e  = (tid < NNODE) ? __expf(m0 - mx) : 0.f;
    s  = blocksum128(e, red);
    float sm0 = e / s;

    mx = blockmax128(ma, red);
    e  = (tid < NNODE) ? __expf(ma - mx) : 0.f;
    s  = blocksum128(e, red);
    float sma = e / s;

    if (tid < NNODE) {
        float a = (g_flag[0] > 0.f) ? (v1 > 0.f ? sm1 : sm0) : sma;
        g_alpha[tid*NNODE + b] = a;
    }
}

// ---------------- E4: hyper messages + y_hat --------------------------
__global__ void hyper_kernel(const float* __restrict__ x_tag,
                             const float* __restrict__ Weo,
                             const float* __restrict__ Wi,
                             const float* __restrict__ bi,
                             float* __restrict__ out, int osz)
{
    const int n = blockIdx.x, tid = threadIdx.x;  // 256
    __shared__ float qa[256], ra[256], nn_s[256], u[256], al[NNODE], red[256];
    qa[tid]   = g_Qa[n*256 + tid];
    ra[tid]   = g_Ra[n*256 + tid];
    nn_s[tid] = g_n[n*256 + tid];
    if (tid < NNODE) al[tid] = g_alpha[n*NNODE + tid];
    __syncthreads();

    float uacc = 0.f, racc = 0.f, alsum = 0.f;
    const float qad = qa[tid];
    for (int j = 0; j < NNODE; j++) {
        float a_ = al[j];
        uacc  += a_ * leaky(g_Qb[j*256 + tid] + qad);
        racc  += a_ * g_Rb[j*256 + tid];
        alsum += a_;
    }
    u[tid] = uacc;
    __syncthreads();

    float T = racc + alsum*ra[tid];
    for (int k = 0; k < 256; k++) T += u[k]*Weo[k*256 + tid];

    const float act = x_tag[n*3+2];
    float hm0 = leaky(act*T);
    float hm1 = leaky((1.f - act)*T);

    const float* Win = Wi + (size_t)n*768*2;
    float p0 = nn_s[tid]*Win[tid*2+0] + hm0*Win[(256+tid)*2+0] + hm1*Win[(512+tid)*2+0];
    float p1 = nn_s[tid]*Win[tid*2+1] + hm0*Win[(256+tid)*2+1] + hm1*Win[(512+tid)*2+1];

    red[tid] = p0; __syncthreads();
    #pragma unroll
    for (int s = 128; s > 0; s >>= 1) { if (tid < s) red[tid] += red[tid+s]; __syncthreads(); }
    float y0 = red[0] + bi[n*2+0]; __syncthreads();

    red[tid] = p1; __syncthreads();
    #pragma unroll
    for (int s = 128; s > 0; s >>= 1) { if (tid < s) red[tid] += red[tid+s]; __syncthreads(); }
    float y1 = red[0] + bi[n*2+1];

    if (tid == 0) {
        float mx = fmaxf(y0, y1);
        float e0 = __expf(y0 - mx), e1 = __expf(y1 - mx);
        int o;
        o = n*2+0; if (o < osz) out[o] = e0/(e0+e1);
        o = n*2+1; if (o < osz) out[o] = e1/(e0+e1);
    }
}

// ---------------- E5: l_ort + l_pol -----------------------------------
__global__ void finals_kernel(const float* __restrict__ x_tag,
                              float* __restrict__ out, int osz)
{
    const int tid = threadIdx.x;  // 256
    __shared__ float red[256], w[NNODE];

    float s1 = 0.f, s2 = 0.f;
    for (int i = tid; i < 16384; i += 256) {
        s1 += g_G[i]          * g_G[16384 + i];
        s2 += g_G[32768 + i]  * g_G[49152 + i];
    }
    red[tid] = s1; __syncthreads();
    #pragma unroll
    for (int s = 128; s > 0; s >>= 1) { if (tid < s) red[tid] += red[tid+s]; __syncthreads(); }
    float S1 = red[0]; __syncthreads();
    red[tid] = s2; __syncthreads();
    #pragma unroll
    for (int s = 128; s > 0; s >>= 1) { if (tid < s) red[tid] += red[tid+s]; __syncthreads(); }
    float S2 = red[0]; __syncthreads();
    if (tid == 0 && 472 < osz) out[472] = sqrtf(S1) + sqrtf(S2);

    if (tid < NNODE) {
        float nr = 0.f;
        const float* np = g_n + tid*256;
        for (int d = 0; d < 256; d++) nr += np[d]*np[d];
        nr = fmaxf(sqrtf(nr), 1e-8f);
        float diff = x_tag[tid*3+1] - x_tag[tid*3+0];
        float sg = (diff > 0.f ? 1.f : (diff < 0.f ? -1.f : 0.f));
        sg *= (x_tag[tid*3+2] == 0.f) ? 1.f : 0.f;
        w[tid] = sg / nr;
    }
    __syncthreads();
    float v = 0.f;
    for (int i = 0; i < NNODE; i++) v += w[i]*g_n[i*256 + tid];
    red[tid] = v*v; __syncthreads();
    #pragma unroll
    for (int s = 128; s > 0; s >>= 1) { if (tid < s) red[tid] += red[tid+s]; __syncthreads(); }
    if (tid == 0 && 473 < osz) out[473] = red[0];
}

// ---------------- launch ----------------------------------------------
extern "C" void kernel_launch(void* const* d_in, const int* in_sizes, int n_in,
                              void* d_out, int out_size)
{
    const float* x       = (const float*)d_in[0];
    const float* x_tag   = (const float*)d_in[1];
    const float* W_ih0   = (const float*)d_in[2];
    const float* W_hh0   = (const float*)d_in[3];
    const float* b_ih0   = (const float*)d_in[4];
    const float* b_hh0   = (const float*)d_in[5];
    const float* W_ih1   = (const float*)d_in[6];
    const float* W_hh1   = (const float*)d_in[7];
    const float* b_ih1   = (const float*)d_in[8];
    const float* b_hh1   = (const float*)d_in[9];
    const float* pm      = (const float*)d_in[10];
    const float* Wum     = (const float*)d_in[11];
    const float* Wvm     = (const float*)d_in[12];
    const float* Wup     = (const float*)d_in[13];
    const float* Wvp     = (const float*)d_in[14];
    const float* W_hyb   = (const float*)d_in[15];
    const float* b_hyb   = (const float*)d_in[16];
    const float* W_act   = (const float*)d_in[17];
    const float* b_act   = (const float*)d_in[18];
    const float* W_inact = (const float*)d_in[19];
    const float* b_inact = (const float*)d_in[20];
    const float* Wphin   = (const float*)d_in[21];
    const float* aphi    = (const float*)d_in[22];
    const float* Won     = (const float*)d_in[23];
    const float* Weo     = (const float*)d_in[24];
    const float* Wi      = (const float*)d_in[25];
    const float* bi      = (const float*)d_in[26];
    float* out = (float*)d_out;

    float *xpre = nullptr, *h1 = nullptr, *h2last = nullptr;
    cudaGetSymbolAddress((void**)&xpre,   g_xpre);
    cudaGetSymbolAddress((void**)&h1,     g_h1);
    cudaGetSymbolAddress((void**)&h2last, g_h2last);

    cudaFuncSetAttribute(gemm_k, cudaFuncAttributeMaxDynamicSharedMemorySize, GEMM_SMEM);

    dim3 gg(4, M_ROWS/128);

    // layer 0
    gemm_k<<<gg, 256, GEMM_SMEM>>>(x, W_ih0, b_ih0, b_hh0, xpre);
    lstm_rec<1><<<NNODE, 512>>>(xpre, W_hh0, h1);
    // layer 1
    gemm_k<<<gg, 256, GEMM_SMEM>>>(h1, W_ih1, b_ih1, b_hh1, xpre);
    lstm_rec<0><<<NNODE, 512>>>(xpre, W_hh1, h2last);

    // epilogue
    prep_kernel<<<1, 128>>>(x_tag, pm, Wvm, out, out_size);
    gram_kernel<<<512, 128>>>(Wum, Wvm, Wup, Wvp);
    node_kernel<<<NNODE, 256>>>(x_tag, Wup, W_hyb, b_hyb, W_act, b_act, W_inact, b_inact);
    proj_kernel<<<NNODE, 256>>>(Wphin, Won, Weo);
    phi_alpha_kernel<<<NNODE, 128>>>(x_tag, aphi);
    hyper_kernel<<<NNODE, 256>>>(x_tag, Weo, Wi, bi, out, out_size);
    finals_kernel<<<1, 256>>>(x_tag, out, out_size);
}

// round 7
// speedup vs baseline: 1.1869x; 1.0521x over previous
#include <cuda_runtime.h>
#include <math.h>

#define NNODE 118
#define TT 2048
#define M_ROWS (NNODE*TT)

typedef unsigned long long ull;
union F2U { ull u; float2 f; };

__device__ __forceinline__ ull pk2(float x, float y){ ull r; asm("mov.b64 %0, {%1,%2};" : "=l"(r) : "f"(x), "f"(y)); return r; }
__device__ __forceinline__ ull dupf(float x){ ull r; asm("mov.b64 %0, {%1,%1};" : "=l"(r) : "f"(x)); return r; }
__device__ __forceinline__ void fma2(ull& d, ull a, ull b){ asm("fma.rn.f32x2 %0, %1, %2, %0;" : "+l"(d) : "l"(a), "l"(b)); }

// unpack bf16x2 word -> f32x2 (low bf16 = even element)
__device__ __forceinline__ ull unpk(unsigned w){
    unsigned lo = w << 16;
    unsigned hi = w & 0xFFFF0000u;
    ull r; asm("mov.b64 %0, {%1,%2};" : "=l"(r) : "r"(lo), "r"(hi));
    return r;
}
__device__ __forceinline__ unsigned bf1(float f){
    unsigned b = __float_as_uint(f);
    return (b + 0x7FFFu + ((b >> 16) & 1u)) >> 16;   // RNE
}
__device__ __forceinline__ unsigned bfpair(float e, float o){ return bf1(e) | (bf1(o) << 16); }

// column permutation: semantic gate-major n (= g*128+c)  <->  stored col' = 4c+g
__device__ __forceinline__ int invperm(int cp){ return (cp & 3)*128 + (cp >> 2); }

// ---------------- scratch (device globals; no allocation allowed) ----------
__device__ __align__(256) float g_xpre[(size_t)M_ROWS*512];
__device__ __align__(256) float g_h1[(size_t)M_ROWS*128];
__device__ __align__(256) float g_h2last[NNODE*128];
__device__ __align__(256) float g_vm[2*128];
__device__ __align__(256) float g_flag[1];
__device__ __align__(256) float g_n[NNODE*256];
__device__ __align__(256) float g_Pa[NNODE*192];
__device__ __align__(256) float g_Pb[NNODE*192];
__device__ __align__(256) float g_Qa[NNODE*256];
__device__ __align__(256) float g_Qb[NNODE*256];
__device__ __align__(256) float g_Ra[NNODE*256];
__device__ __align__(256) float g_Rb[NNODE*256];
__device__ __align__(256) float g_alpha[NNODE*NNODE];
__device__ __align__(256) float g_G[4*128*128];

__device__ __forceinline__ float leaky(float z){ return z >= 0.f ? z : 0.01f*z; }

// ---------------- GEMM: C(M,512) = A(M,128) @ W(512,128)^T + b1 + b2 -------
// Output columns PERMUTED: stored col' = 4c+g for semantic n = g*128+c.
#define GP2 132
#define GEMM_SMEM (2*128*GP2*4)

__global__ void __launch_bounds__(256) gemm_k(const float* __restrict__ A,
                                              const float* __restrict__ W,
                                              const float* __restrict__ b1,
                                              const float* __restrict__ b2,
                                              float* __restrict__ C)
{
    extern __shared__ float sm[];
    float* As = sm;               // [k][m] pad GP2
    float* Ws = sm + 128*GP2;     // [k][n'] pad GP2
    const int tid = threadIdx.x;
    const int mbase = blockIdx.y * 128;
    const int nbase = blockIdx.x * 128;

    const float4* A4 = (const float4*)(A + (size_t)mbase*128);
    const float4* W4 = (const float4*)W;
    #pragma unroll
    for (int r = 0; r < 16; r++) {
        int idx = tid + r*256;          // 0..4095
        int row = idx >> 5;             // 0..127
        int kg  = idx & 31;             // 0..31
        float4 va = A4[idx];
        As[(4*kg+0)*GP2 + row] = va.x;
        As[(4*kg+1)*GP2 + row] = va.y;
        As[(4*kg+2)*GP2 + row] = va.z;
        As[(4*kg+3)*GP2 + row] = va.w;
        int srow = invperm(nbase + row);      // permuted W row source
        float4 vw = W4[srow*32 + kg];
        Ws[(4*kg+0)*GP2 + row] = vw.x;
        Ws[(4*kg+1)*GP2 + row] = vw.y;
        Ws[(4*kg+2)*GP2 + row] = vw.z;
        Ws[(4*kg+3)*GP2 + row] = vw.w;
    }
    __syncthreads();

    const int tx = tid & 15;   // n micro
    const int ty = tid >> 4;   // m micro
    const int m0 = ty*8, n0 = tx*8;

    F2U acc[4][8];
    #pragma unroll
    for (int p = 0; p < 4; p++)
        #pragma unroll
        for (int j = 0; j < 8; j++) acc[p][j].u = 0ull;

    #pragma unroll 8
    for (int k = 0; k < 128; k++) {
        const float4 a0 = *(const float4*)(As + k*GP2 + m0);
        const float4 a1 = *(const float4*)(As + k*GP2 + m0 + 4);
        const float4 w0 = *(const float4*)(Ws + k*GP2 + n0);
        const float4 w1 = *(const float4*)(Ws + k*GP2 + n0 + 4);
        ull ap0 = pk2(a0.x, a0.y), ap1 = pk2(a0.z, a0.w);
        ull ap2 = pk2(a1.x, a1.y), ap3 = pk2(a1.z, a1.w);
        ull wd;
        wd = dupf(w0.x); fma2(acc[0][0].u, ap0, wd); fma2(acc[1][0].u, ap1, wd); fma2(acc[2][0].u, ap2, wd); fma2(acc[3][0].u, ap3, wd);
        wd = dupf(w0.y); fma2(acc[0][1].u, ap0, wd); fma2(acc[1][1].u, ap1, wd); fma2(acc[2][1].u, ap2, wd); fma2(acc[3][1].u, ap3, wd);
        wd = dupf(w0.z); fma2(acc[0][2].u, ap0, wd); fma2(acc[1][2].u, ap1, wd); fma2(acc[2][2].u, ap2, wd); fma2(acc[3][2].u, ap3, wd);
        wd = dupf(w0.w); fma2(acc[0][3].u, ap0, wd); fma2(acc[1][3].u, ap1, wd); fma2(acc[2][3].u, ap2, wd); fma2(acc[3][3].u, ap3, wd);
        wd = dupf(w1.x); fma2(acc[0][4].u, ap0, wd); fma2(acc[1][4].u, ap1, wd); fma2(acc[2][4].u, ap2, wd); fma2(acc[3][4].u, ap3, wd);
        wd = dupf(w1.y); fma2(acc[0][5].u, ap0, wd); fma2(acc[1][5].u, ap1, wd); fma2(acc[2][5].u, ap2, wd); fma2(acc[3][5].u, ap3, wd);
        wd = dupf(w1.z); fma2(acc[0][6].u, ap0, wd); fma2(acc[1][6].u, ap1, wd); fma2(acc[2][6].u, ap2, wd); fma2(acc[3][6].u, ap3, wd);
        wd = dupf(w1.w); fma2(acc[0][7].u, ap0, wd); fma2(acc[1][7].u, ap1, wd); fma2(acc[2][7].u, ap2, wd); fma2(acc[3][7].u, ap3, wd);
    }

    const int col = nbase + n0;
    float bias[8];
    #pragma unroll
    for (int c = 0; c < 8; c++) {
        int src = invperm(col + c);
        bias[c] = b1[src] + b2[src];
    }

    #pragma unroll
    for (int p = 0; p < 4; p++) {
        float4 o;
        float* r0 = C + (size_t)(mbase + m0 + 2*p)*512 + col;
        float* r1 = r0 + 512;
        o.x = acc[p][0].f.x + bias[0]; o.y = acc[p][1].f.x + bias[1];
        o.z = acc[p][2].f.x + bias[2]; o.w = acc[p][3].f.x + bias[3];
        *(float4*)(r0) = o;
        o.x = acc[p][4].f.x + bias[4]; o.y = acc[p][5].f.x + bias[5];
        o.z = acc[p][6].f.x + bias[6]; o.w = acc[p][7].f.x + bias[7];
        *(float4*)(r0 + 4) = o;
        o.x = acc[p][0].f.y + bias[0]; o.y = acc[p][1].f.y + bias[1];
        o.z = acc[p][2].f.y + bias[2]; o.w = acc[p][3].f.y + bias[3];
        *(float4*)(r1) = o;
        o.x = acc[p][4].f.y + bias[4]; o.y = acc[p][5].f.y + bias[5];
        o.z = acc[p][6].f.y + bias[6]; o.w = acc[p][7].f.y + bias[7];
        *(float4*)(r1 + 4) = o;
    }
}

// ---------------- LSTM recurrence: one block per node ----------------------
// xpre columns are permuted (col' = 4c+g), so thread j reads column j —
// coalesced. Quad {i,f,g,o} of a cell = 4 consecutive lanes -> SHFL update,
// ONE barrier/step, h double-buffered. k=0..87 fp32 in regs, 88..127 bf16 smem.
template<int WRITE_ALL>
__global__ void __launch_bounds__(512, 1) lstm_rec(const float* __restrict__ xpre,
                                                   const float* __restrict__ Whh,
                                                   float* __restrict__ hout)
{
    __shared__ __align__(16) float hs[2][128];
    __shared__ __align__(16) uint4 wsb[5*512];   // 40 KB bf16 weight slice

    const int j = threadIdx.x;
    const int n = blockIdx.x;
    const int l = j & 31;
    const int w = j >> 5;
    const int gate = l & 3;
    const int cell = w*8 + (l >> 2);
    const int row  = gate*128 + cell;            // = invperm(j)

    // load weights: row `row` of Whh (128 floats)
    const float* wg = Whh + row*128;
    ull wr[44];                                   // k = 0..87
    #pragma unroll
    for (int g = 0; g < 22; g++) {
        float4 v = *(const float4*)(wg + 4*g);
        wr[2*g]   = pk2(v.x, v.y);
        wr[2*g+1] = pk2(v.z, v.w);
    }
    #pragma unroll
    for (int s = 0; s < 5; s++) {                 // k = 88..127 as bf16
        const float* base = wg + 88 + s*8;
        uint4 pk;
        pk.x = bfpair(base[0], base[1]);
        pk.y = bfpair(base[2], base[3]);
        pk.z = bfpair(base[4], base[5]);
        pk.w = bfpair(base[6], base[7]);
        wsb[s*512 + j] = pk;
    }

    if (j < 128) hs[0][j] = 0.f;
    float c = 0.f;
    __syncthreads();

    const float* xp = xpre + (size_t)n*TT*512 + j;   // coalesced (permuted layout)
    float xnext = xp[0];
    float* hw = hout + (WRITE_ALL ? ((size_t)n*TT*128 + cell) : ((size_t)n*128 + cell));

    int p = 0;
    for (int t = 0; t < TT; t++) {
        F2U A0, A1, A2, A3;
        A0.u = pk2(xnext, 0.f); A1.u = 0ull; A2.u = 0ull; A3.u = 0ull;
        if (t + 1 < TT) xnext = xp[(size_t)(t+1)*512];

        const ulonglong2* h2 = (const ulonglong2*)hs[p];
        #pragma unroll
        for (int g = 0; g < 22; g += 2) {            // k = 0..87
            ulonglong2 hv0 = h2[g];
            ulonglong2 hv1 = h2[g+1];
            fma2(A0.u, wr[2*g],   hv0.x);
            fma2(A1.u, wr[2*g+1], hv0.y);
            fma2(A2.u, wr[2*g+2], hv1.x);
            fma2(A3.u, wr[2*g+3], hv1.y);
        }
        #pragma unroll
        for (int s = 0; s < 5; s++) {                // k = 88..127
            uint4 wv = wsb[s*512 + j];
            ulonglong2 hv0 = h2[22 + 2*s];
            ulonglong2 hv1 = h2[23 + 2*s];
            fma2(A0.u, unpk(wv.x), hv0.x);
            fma2(A1.u, unpk(wv.y), hv0.y);
            fma2(A2.u, unpk(wv.z), hv1.x);
            fma2(A3.u, unpk(wv.w), hv1.y);
        }
        float acc = (A0.f.x + A0.f.y) + (A1.f.x + A1.f.y)
                  + (A2.f.x + A2.f.y) + (A3.f.x + A3.f.y);

        // branch-free activation: sigmoid for i,f,o; tanh = 2*sig(2x)-1 for g
        const bool isg = (gate == 2);
        float u  = isg ? 2.f*acc : acc;
        float e  = __expf(-u);
        float s_ = __fdividef(1.f, 1.f + e);
        float a  = isg ? (2.f*s_ - 1.f) : s_;

        const int base = l & ~3;
        float iv = __shfl_sync(0xFFFFFFFFu, a, base);
        float fv = __shfl_sync(0xFFFFFFFFu, a, base + 1);
        float gv = __shfl_sync(0xFFFFFFFFu, a, base + 2);
        float ov = __shfl_sync(0xFFFFFFFFu, a, base + 3);
        c = fv*c + iv*gv;
        float e2 = __expf(-2.f*c);
        float th = __fdividef(2.f, 1.f + e2) - 1.f;
        float hv = ov * th;
        p ^= 1;
        if (gate == 0) {
            hs[p][cell] = hv;
            if (WRITE_ALL)      hw[(size_t)t*128] = hv;
            else if (t == TT-1) hw[0] = hv;
        }
        __syncthreads();
    }
}

// ---------------- E0: pseudo-message projections + direct outputs ----------
__global__ void prep_kernel(const float* __restrict__ x_tag,
                            const float* __restrict__ pm,
                            const float* __restrict__ Wvm,
                            float* __restrict__ out, int osz)
{
    const int tid = threadIdx.x;  // 128
    __shared__ float pms[768];
    for (int i = tid; i < 768; i += 128) pms[i] = pm[i];
    __syncthreads();

    float base = 0.f;
    for (int k = 0; k < 768; k++) base += pms[k]*Wvm[k*128 + tid];
    g_vm[tid]       = leaky(base);
    g_vm[128 + tid] = leaky(base + Wvm[768*128 + tid]);

    if (tid < NNODE) {
        int o;
        o = 236 + tid*2 + 0; if (o < osz) out[o] = x_tag[tid*3+0];
        o = 236 + tid*2 + 1; if (o < osz) out[o] = x_tag[tid*3+1];
        float a = x_tag[tid*3+2];
        o = 474 + tid; if (o < osz) out[o] = (a == 0.f) ? 1.f : 0.f;
        o = 592 + tid; if (o < osz) out[o] = (a == 1.f) ? 1.f : 0.f;
    }
    if (tid == 0) {
        int cnt = 0;
        for (int i = 0; i < NNODE; i++) if (x_tag[i*3+2] == 0.f) cnt++;
        g_flag[0] = (cnt > 0) ? 1.f : 0.f;
    }
}

// ---------------- Gram matrices for l_ort -----------------------------
__global__ void gram_kernel(const float* __restrict__ Wum, const float* __restrict__ Wvm,
                            const float* __restrict__ Wup, const float* __restrict__ Wvp)
{
    const int bid = blockIdx.x;
    const int mat = bid >> 7;
    const int k   = bid & 127;
    const int l   = threadIdx.x;  // 128
    const float* W; int rows;
    if      (mat == 0) { W = Wum; rows = 769; }
    else if (mat == 1) { W = Wvm; rows = 769; }
    else if (mat == 2) { W = Wup; rows = 128; }
    else               { W = Wvp; rows = 128; }
    float acc = 0.f;
    for (int i = 0; i < rows; i++) acc += W[i*128 + k] * W[i*128 + l];
    g_G[mat*16384 + k*128 + l] = acc;
}

// ---------------- E1: per-node MLP chain -> n -------------------------
__global__ void node_kernel(const float* __restrict__ x_tag,
                            const float* __restrict__ Wup,
                            const float* __restrict__ W_hyb, const float* __restrict__ b_hyb,
                            const float* __restrict__ W_act, const float* __restrict__ b_act,
                            const float* __restrict__ W_inact, const float* __restrict__ b_inact)
{
    const int n = blockIdx.x, tid = threadIdx.x;  // 256
    __shared__ float p[128], up[128], vm_s[128], hh[256];
    const float act = x_tag[n*3+2];
    if (tid < 128) {
        p[tid]    = leaky(g_h2last[n*128 + tid]);
        vm_s[tid] = (act == 1.f) ? g_vm[128 + tid] : g_vm[tid];
    }
    __syncthreads();
    if (tid < 128) {
        float a = 0.f;
        for (int k = 0; k < 128; k++) a += p[k]*Wup[k*128 + tid];
        up[tid] = leaky(a);
    }
    __syncthreads();
    {
        float a = b_hyb[tid];
        for (int k = 0; k < 128; k++) {
            float u_ = up[k], v_ = vm_s[k];
            a += u_*W_hyb[k*256 + tid] + (u_ + v_)*W_hyb[(128+k)*256 + tid] + v_*W_hyb[(256+k)*256 + tid];
        }
        hh[tid] = leaky(a);
    }
    __syncthreads();
    {
        float na = b_act[tid], ni = b_inact[tid];
        for (int k = 0; k < 256; k++) {
            float h_ = hh[k];
            na += h_*W_act[k*256 + tid];
            ni += h_*W_inact[k*256 + tid];
        }
        na += x_tag[n*3+0]*W_act[256*256 + tid] + x_tag[n*3+1]*W_act[257*256 + tid];
        g_n[n*256 + tid] = leaky(na*(1.f - act) + ni*act);
    }
}

// ---------------- E2: per-node pair projections -----------------------
__global__ void proj_kernel(const float* __restrict__ Wphin,
                            const float* __restrict__ Won,
                            const float* __restrict__ Weo)
{
    const int n = blockIdx.x, tid = threadIdx.x;  // 256
    __shared__ float nn_s[256];
    nn_s[tid] = g_n[n*256 + tid];
    __syncthreads();
    if (tid < 192) {
        float pb = 0.f, pa = 0.f;
        for (int k = 0; k < 256; k++) {
            float v = nn_s[k];
            pb += v*Wphin[k*192 + tid];
            pa += v*Wphin[(256+k)*192 + tid];
        }
        g_Pb[n*192 + tid] = pb;
        g_Pa[n*192 + tid] = pa;
    }
    float qb = 0.f, qa = 0.f, rb = 0.f, ra = 0.f;
    for (int k = 0; k < 256; k++) {
        float v = nn_s[k];
        qb += v*Won[k*256 + tid];
        qa += v*Won[(256+k)*256 + tid];
        rb += v*Weo[(256+k)*256 + tid];
        ra += v*Weo[(512+k)*256 + tid];
    }
    g_Qb[n*256 + tid] = qb;
    g_Qa[n*256 + tid] = qa;
    g_Rb[n*256 + tid] = rb;
    g_Ra[n*256 + tid] = ra;
}

// ---------------- E3: phi column + masked softmaxes -> alpha ----------
__device__ __forceinline__ float blockmax128(float v, float* red){
    int tid = threadIdx.x; red[tid] = v; __syncthreads();
    #pragma unroll
    for (int s = 64; s > 0; s >>= 1) { if (tid < s) red[tid] = fmaxf(red[tid], red[tid+s]); __syncthreads(); }
    float r = red[0]; __syncthreads(); return r;
}
__device__ __forceinline__ float blocksum128(float v, float* red){
    int tid = threadIdx.x; red[tid] = v; __syncthreads();
    #pragma unroll
    for (int s = 64; s > 0; s >>= 1) { if (tid < s) red[tid] += red[tid+s]; __syncthreads(); }
    float r = red[0]; __syncthreads(); return r;
}

__global__ void phi_alpha_kernel(const float* __restrict__ x_tag,
                                 const float* __restrict__ aphi)
{
    const int b = blockIdx.x;
    const int tid = threadIdx.x;  // 128
    __shared__ float pb_s[192], ap_s[192], red[128];
    for (int i = tid; i < 192; i += 128) { pb_s[i] = g_Pb[b*192 + i]; ap_s[i] = aphi[i]; }
    __syncthreads();

    float ph = 0.f, v1 = 0.f;
    if (tid < NNODE) {
        const float* pa = g_Pa + tid*192;
        #pragma unroll 8
        for (int d = 0; d < 192; d++) ph += leaky(pb_s[d] + pa[d]) * ap_s[d];
        v1 = (x_tag[tid*3+2] == 0.f) ? 1.f : 0.f;
    }

    const float NEG = -1000000000.f;
    float m1 = (tid < NNODE) ? (v1 > 0.f ? ph : NEG) : -INFINITY;
    float m0 = (tid < NNODE) ? (v1 > 0.f ? NEG : ph) : -INFINITY;
    float ma = (tid < NNODE) ? ph : -INFINITY;

    float mx = blockmax128(m1, red);
    float e  = (tid < NNODE) ? __expf(m1 - mx) : 0.f;
    float s  = blocksum128(e, red);
    float sm1 = e / s;

    mx = blockmax128(m0, red);
    e  = (tid < NNODE) ? __expf(m0 - mx) : 0.f;
    s  = blocksum128(e, red);
    float sm0 = e / s;

    mx = blockmax128(ma, red);
    e  = (tid < NNODE) ? __expf(ma - mx) : 0.f;
    s  = blocksum128(e, red);
    float sma = e / s;

    if (tid < NNODE) {
        float a = (g_flag[0] > 0.f) ? (v1 > 0.f ? sm1 : sm0) : sma;
        g_alpha[tid*NNODE + b] = a;
    }
}

// ---------------- E4: hyper messages + y_hat --------------------------
__global__ void hyper_kernel(const float* __restrict__ x_tag,
                             const float* __restrict__ Weo,
                             const float* __restrict__ Wi,
                             const float* __restrict__ bi,
                             float* __restrict__ out, int osz)
{
    const int n = blockIdx.x, tid = threadIdx.x;  // 256
    __shared__ float qa[256], ra[256], nn_s[256], u[256], al[NNODE], red[256];
    qa[tid]   = g_Qa[n*256 + tid];
    ra[tid]   = g_Ra[n*256 + tid];
    nn_s[tid] = g_n[n*256 + tid];
    if (tid < NNODE) al[tid] = g_alpha[n*NNODE + tid];
    __syncthreads();

    float uacc = 0.f, racc = 0.f, alsum = 0.f;
    const float qad = qa[tid];
    for (int j = 0; j < NNODE; j++) {
        float a_ = al[j];
        uacc  += a_ * leaky(g_Qb[j*256 + tid] + qad);
        racc  += a_ * g_Rb[j*256 + tid];
        alsum += a_;
    }
    u[tid] = uacc;
    __syncthreads();

    float T = racc + alsum*ra[tid];
    for (int k = 0; k < 256; k++) T += u[k]*Weo[k*256 + tid];

    const float act = x_tag[n*3+2];
    float hm0 = leaky(act*T);
    float hm1 = leaky((1.f - act)*T);

    const float* Win = Wi + (size_t)n*768*2;
    float p0 = nn_s[tid]*Win[tid*2+0] + hm0*Win[(256+tid)*2+0] + hm1*Win[(512+tid)*2+0];
    float p1 = nn_s[tid]*Win[tid*2+1] + hm0*Win[(256+tid)*2+1] + hm1*Win[(512+tid)*2+1];

    red[tid] = p0; __syncthreads();
    #pragma unroll
    for (int s = 128; s > 0; s >>= 1) { if (tid < s) red[tid] += red[tid+s]; __syncthreads(); }
    float y0 = red[0] + bi[n*2+0]; __syncthreads();

    red[tid] = p1; __syncthreads();
    #pragma unroll
    for (int s = 128; s > 0; s >>= 1) { if (tid < s) red[tid] += red[tid+s]; __syncthreads(); }
    float y1 = red[0] + bi[n*2+1];

    if (tid == 0) {
        float mx = fmaxf(y0, y1);
        float e0 = __expf(y0 - mx), e1 = __expf(y1 - mx);
        int o;
        o = n*2+0; if (o < osz) out[o] = e0/(e0+e1);
        o = n*2+1; if (o < osz) out[o] = e1/(e0+e1);
    }
}

// ---------------- E5: l_ort + l_pol -----------------------------------
__global__ void finals_kernel(const float* __restrict__ x_tag,
                              float* __restrict__ out, int osz)
{
    const int tid = threadIdx.x;  // 256
    __shared__ float red[256], w[NNODE];

    float s1 = 0.f, s2 = 0.f;
    for (int i = tid; i < 16384; i += 256) {
        s1 += g_G[i]          * g_G[16384 + i];
        s2 += g_G[32768 + i]  * g_G[49152 + i];
    }
    red[tid] = s1; __syncthreads();
    #pragma unroll
    for (int s = 128; s > 0; s >>= 1) { if (tid < s) red[tid] += red[tid+s]; __syncthreads(); }
    float S1 = red[0]; __syncthreads();
    red[tid] = s2; __syncthreads();
    #pragma unroll
    for (int s = 128; s > 0; s >>= 1) { if (tid < s) red[tid] += red[tid+s]; __syncthreads(); }
    float S2 = red[0]; __syncthreads();
    if (tid == 0 && 472 < osz) out[472] = sqrtf(S1) + sqrtf(S2);

    if (tid < NNODE) {
        float nr = 0.f;
        const float* np = g_n + tid*256;
        for (int d = 0; d < 256; d++) nr += np[d]*np[d];
        nr = fmaxf(sqrtf(nr), 1e-8f);
        float diff = x_tag[tid*3+1] - x_tag[tid*3+0];
        float sg = (diff > 0.f ? 1.f : (diff < 0.f ? -1.f : 0.f));
        sg *= (x_tag[tid*3+2] == 0.f) ? 1.f : 0.f;
        w[tid] = sg / nr;
    }
    __syncthreads();
    float v = 0.f;
    for (int i = 0; i < NNODE; i++) v += w[i]*g_n[i*256 + tid];
    red[tid] = v*v; __syncthreads();
    #pragma unroll
    for (int s = 128; s > 0; s >>= 1) { if (tid < s) red[tid] += red[tid+s]; __syncthreads(); }
    if (tid == 0 && 473 < osz) out[473] = red[0];
}

// ---------------- launch ----------------------------------------------
extern "C" void kernel_launch(void* const* d_in, const int* in_sizes, int n_in,
                              void* d_out, int out_size)
{
    const float* x       = (const float*)d_in[0];
    const float* x_tag   = (const float*)d_in[1];
    const float* W_ih0   = (const float*)d_in[2];
    const float* W_hh0   = (const float*)d_in[3];
    const float* b_ih0   = (const float*)d_in[4];
    const float* b_hh0   = (const float*)d_in[5];
    const float* W_ih1   = (const float*)d_in[6];
    const float* W_hh1   = (const float*)d_in[7];
    const float* b_ih1   = (const float*)d_in[8];
    const float* b_hh1   = (const float*)d_in[9];
    const float* pm      = (const float*)d_in[10];
    const float* Wum     = (const float*)d_in[11];
    const float* Wvm     = (const float*)d_in[12];
    const float* Wup     = (const float*)d_in[13];
    const float* Wvp     = (const float*)d_in[14];
    const float* W_hyb   = (const float*)d_in[15];
    const float* b_hyb   = (const float*)d_in[16];
    const float* W_act   = (const float*)d_in[17];
    const float* b_act   = (const float*)d_in[18];
    const float* W_inact = (const float*)d_in[19];
    const float* b_inact = (const float*)d_in[20];
    const float* Wphin   = (const float*)d_in[21];
    const float* aphi    = (const float*)d_in[22];
    const float* Won     = (const float*)d_in[23];
    const float* Weo     = (const float*)d_in[24];
    const float* Wi      = (const float*)d_in[25];
    const float* bi      = (const float*)d_in[26];
    float* out = (float*)d_out;

    float *xpre = nullptr, *h1 = nullptr, *h2last = nullptr;
    cudaGetSymbolAddress((void**)&xpre,   g_xpre);
    cudaGetSymbolAddress((void**)&h1,     g_h1);
    cudaGetSymbolAddress((void**)&h2last, g_h2last);

    cudaFuncSetAttribute(gemm_k, cudaFuncAttributeMaxDynamicSharedMemorySize, GEMM_SMEM);

    dim3 gg(4, M_ROWS/128);

    // layer 0
    gemm_k<<<gg, 256, GEMM_SMEM>>>(x, W_ih0, b_ih0, b_hh0, xpre);
    lstm_rec<1><<<NNODE, 512>>>(xpre, W_hh0, h1);
    // layer 1
    gemm_k<<<gg, 256, GEMM_SMEM>>>(h1, W_ih1, b_ih1, b_hh1, xpre);
    lstm_rec<0><<<NNODE, 512>>>(xpre, W_hh1, h2last);

    // epilogue
    prep_kernel<<<1, 128>>>(x_tag, pm, Wvm, out, out_size);
    gram_kernel<<<512, 128>>>(Wum, Wvm, Wup, Wvp);
    node_kernel<<<NNODE, 256>>>(x_tag, Wup, W_hyb, b_hyb, W_act, b_act, W_inact, b_inact);
    proj_kernel<<<NNODE, 256>>>(Wphin, Won, Weo);
    phi_alpha_kernel<<<NNODE, 128>>>(x_tag, aphi);
    hyper_kernel<<<NNODE, 256>>>(x_tag, Weo, Wi, bi, out, out_size);
    finals_kernel<<<1, 256>>>(x_tag, out, out_size);
}